// round 8
// baseline (speedup 1.0000x reference)
#include <cuda_runtime.h>
#include <cuda_bf16.h>
#include <cstdint>

// Problem constants
constexpr int Bn  = 2;
constexpr int Ln  = 2048;
constexpr int Dn  = 1024;
constexpr int Hn  = 16;
constexpr int HDn = 64;
constexpr int NROW = Bn * Ln;   // 4096
constexpr size_t PLANE = (size_t)Bn * Hn * Ln * HDn;  // 4M elems

// Fixed-point scales (x,q,k,v have sigma~1; W sigma = 1/32)
constexpr float QS_X = 3008.f;
constexpr float QS_W = 96256.f;
constexpr float INV8 = 1.f / (QS_X * QS_W);

// Scratch (device globals: allocation-free)
__device__ int8_t   g_x8h[(size_t)NROW * Dn];     // x int8 hi, [m][k]
__device__ int8_t   g_x8l[(size_t)NROW * Dn];     // x int8 lo
__device__ int8_t   g_w8h[(size_t)3 * Dn * Dn];   // Wq/k/v int8 hi, TRANSPOSED [n][k]
__device__ int8_t   g_w8l[(size_t)3 * Dn * Dn];
__device__ uint16_t g_wh[(size_t)Dn * Dn];        // Wo bf16 hi, [k][n]
__device__ uint16_t g_wl[(size_t)Dn * Dn];
__device__ uint16_t g_qkvh[3 * PLANE];            // [3][B][H][L][HD] bf16
__device__ uint16_t g_qkvl[3 * PLANE];
__device__ uint16_t g_yh[(size_t)NROW * Dn];      // attn out bf16, col = h*64+hd
__device__ uint16_t g_yl[(size_t)NROW * Dn];

// ---------------------------------------------------------------------------
// Helpers
// ---------------------------------------------------------------------------
__device__ __forceinline__ uint32_t s2u(const void* p) {
    uint32_t a;
    asm("{ .reg .u64 t; cvta.to.shared.u64 t, %1; cvt.u32.u64 %0, t; }"
        : "=r"(a) : "l"(p));
    return a;
}
__device__ __forceinline__ void cp16(uint32_t dst, const void* src) {
    asm volatile("cp.async.cg.shared.global [%0], [%1], 16;"
                 :: "r"(dst), "l"(src) : "memory");
}
#define CP_COMMIT() asm volatile("cp.async.commit_group;" ::: "memory")
#define CP_WAIT0()  asm volatile("cp.async.wait_group 0;" ::: "memory")
#define CP_WAIT1()  asm volatile("cp.async.wait_group 1;" ::: "memory")

__device__ __forceinline__ void ldm_x4(uint32_t* r, uint32_t a) {
    asm volatile("ldmatrix.sync.aligned.m8n8.x4.shared.b16 {%0,%1,%2,%3}, [%4];"
                 : "=r"(r[0]), "=r"(r[1]), "=r"(r[2]), "=r"(r[3]) : "r"(a));
}
__device__ __forceinline__ void ldm_x4t(uint32_t* r, uint32_t a) {
    asm volatile("ldmatrix.sync.aligned.m8n8.x4.trans.shared.b16 {%0,%1,%2,%3}, [%4];"
                 : "=r"(r[0]), "=r"(r[1]), "=r"(r[2]), "=r"(r[3]) : "r"(a));
}
__device__ __forceinline__ void mma_bf16(float* c, const uint32_t* a,
                                         const uint32_t* b) {
    asm volatile(
        "mma.sync.aligned.m16n8k16.row.col.f32.bf16.bf16.f32 "
        "{%0,%1,%2,%3}, {%4,%5,%6,%7}, {%8,%9}, {%0,%1,%2,%3};"
        : "+f"(c[0]), "+f"(c[1]), "+f"(c[2]), "+f"(c[3])
        : "r"(a[0]), "r"(a[1]), "r"(a[2]), "r"(a[3]), "r"(b[0]), "r"(b[1]));
}
__device__ __forceinline__ void mma_s8(int* c, const uint32_t* a,
                                       const uint32_t* b) {
    asm volatile(
        "mma.sync.aligned.m16n8k32.row.col.s32.s8.s8.s32 "
        "{%0,%1,%2,%3}, {%4,%5,%6,%7}, {%8,%9}, {%0,%1,%2,%3};"
        : "+r"(c[0]), "+r"(c[1]), "+r"(c[2]), "+r"(c[3])
        : "r"(a[0]), "r"(a[1]), "r"(a[2]), "r"(a[3]), "r"(b[0]), "r"(b[1]));
}
__device__ __forceinline__ uint16_t bfu(float f) {
    __nv_bfloat16 h = __float2bfloat16_rn(f);
    return *(uint16_t*)&h;
}
__device__ __forceinline__ float bff(uint16_t u) {
    __nv_bfloat16 h = *(__nv_bfloat16*)&u;
    return __bfloat162float(h);
}
__device__ __forceinline__ void split4(float4 v, uint2& hi, uint2& lo) {
    uint16_t h0 = bfu(v.x), h1 = bfu(v.y), h2 = bfu(v.z), h3 = bfu(v.w);
    uint16_t l0 = bfu(v.x - bff(h0)), l1 = bfu(v.y - bff(h1));
    uint16_t l2 = bfu(v.z - bff(h2)), l3 = bfu(v.w - bff(h3));
    hi = make_uint2((uint32_t)h0 | ((uint32_t)h1 << 16),
                    (uint32_t)h2 | ((uint32_t)h3 << 16));
    lo = make_uint2((uint32_t)l0 | ((uint32_t)l1 << 16),
                    (uint32_t)l2 | ((uint32_t)l3 << 16));
}
__device__ __forceinline__ void packhl(float f0, float f1,
                                       uint32_t& h2, uint32_t& l2) {
    uint16_t h0 = bfu(f0), h1 = bfu(f1);
    uint16_t l0 = bfu(f0 - bff(h0)), l1 = bfu(f1 - bff(h1));
    h2 = (uint32_t)h0 | ((uint32_t)h1 << 16);
    l2 = (uint32_t)l0 | ((uint32_t)l1 << 16);
}
// 15-bit fixed-point quantize: x*s -> h*128 + l
__device__ __forceinline__ void quant1(float x, float s, int& h, int& l) {
    int q = __float2int_rn(x * s);
    q = ::max(-16255, ::min(16255, q));
    h = (q + 64) >> 7;
    l = q - (h << 7);
}
__device__ __forceinline__ uint32_t packb(int b0, int b1, int b2, int b3) {
    return (uint32_t)(uint8_t)b0 | ((uint32_t)(uint8_t)b1 << 8)
         | ((uint32_t)(uint8_t)b2 << 16) | ((uint32_t)(uint8_t)b3 << 24);
}

// ---------------------------------------------------------------------------
// Prep: quantize x (int8 h/l, [m][k]); quantize+TRANSPOSE Wq/k/v (int8, [n][k]);
// bf16-split Wo. Grid: [0,4096) x, [4096,4864) W-transpose, [4864,5888) Wo.
// ---------------------------------------------------------------------------
__global__ void __launch_bounds__(256) prep_kernel(
    const float* __restrict__ x,
    const float* __restrict__ Wq, const float* __restrict__ Wk,
    const float* __restrict__ Wv, const float* __restrict__ Wo)
{
    __shared__ uint8_t sh[64][68];
    __shared__ uint8_t sl[64][68];
    const int bid = blockIdx.x;
    const int tid = threadIdx.x;

    if (bid < 4096) {
        // x: 1 float4 per thread
        int i = bid * 256 + tid;
        float4 v = ((const float4*)x)[i];
        int h0, l0, h1, l1, h2, l2, h3, l3;
        quant1(v.x, QS_X, h0, l0); quant1(v.y, QS_X, h1, l1);
        quant1(v.z, QS_X, h2, l2); quant1(v.w, QS_X, h3, l3);
        ((uint32_t*)g_x8h)[i] = packb(h0, h1, h2, h3);
        ((uint32_t*)g_x8l)[i] = packb(l0, l1, l2, l3);
    } else if (bid < 4864) {
        // Wq/Wk/Wv: 64x64 tile transpose-quantize
        int j = bid - 4096;
        int widx = j >> 8;              // 0..2
        int tile = j & 255;
        int tk = (tile >> 4) * 64, tn = (tile & 15) * 64;
        const float* W = (widx == 0) ? Wq : (widx == 1) ? Wk : Wv;
        #pragma unroll
        for (int it = 0; it < 4; it++) {
            int r = it * 16 + (tid >> 4);
            int c4 = (tid & 15) * 4;
            float4 v = *(const float4*)(W + (size_t)(tk + r) * Dn + tn + c4);
            int h, l;
            quant1(v.x, QS_W, h, l); sh[r][c4+0] = (uint8_t)h; sl[r][c4+0] = (uint8_t)l;
            quant1(v.y, QS_W, h, l); sh[r][c4+1] = (uint8_t)h; sl[r][c4+1] = (uint8_t)l;
            quant1(v.z, QS_W, h, l); sh[r][c4+2] = (uint8_t)h; sl[r][c4+2] = (uint8_t)l;
            quant1(v.w, QS_W, h, l); sh[r][c4+3] = (uint8_t)h; sl[r][c4+3] = (uint8_t)l;
        }
        __syncthreads();
        int8_t* wh = g_w8h + (size_t)widx * Dn * Dn;
        int8_t* wl = g_w8l + (size_t)widx * Dn * Dn;
        #pragma unroll
        for (int it = 0; it < 4; it++) {
            int n  = it * 16 + (tid >> 4);
            int k4 = (tid & 15) * 4;
            uint32_t hw = packb(sh[k4+0][n], sh[k4+1][n], sh[k4+2][n], sh[k4+3][n]);
            uint32_t lw = packb(sl[k4+0][n], sl[k4+1][n], sl[k4+2][n], sl[k4+3][n]);
            size_t off = (size_t)(tn + n) * Dn + tk + k4;
            *(uint32_t*)(wh + off) = hw;
            *(uint32_t*)(wl + off) = lw;
        }
    } else {
        // Wo: bf16 split, 1 float4 per thread
        int i = (bid - 4864) * 256 + tid;
        float4 v = ((const float4*)Wo)[i];
        uint2 hi, lo;
        split4(v, hi, lo);
        ((uint2*)g_wh)[i] = hi;
        ((uint2*)g_wl)[i] = lo;
    }
}

// ---------------------------------------------------------------------------
// int8 QKV GEMM: 128x64 CTA tile, 8 warps (4m x 2n), warp tile 32x32, BK=64.
// A = x int8 h/l [m][k]; B = W^T int8 h/l [n][k]. Exact s32 accumulation:
// acc_hh (weight 16384) and acc_mid (hl + lh, weight 128); l*l dropped.
// 3-stage cp.async. Stage: Ah 0 (10240), Al 10240, Bh 20480 (5120), Bl 25600.
// Stage 30720 B x3 = 92160. 2 CTAs/SM.
// ---------------------------------------------------------------------------
constexpr int G8_STAGE = 30720;
constexpr int G8_SMEM  = 3 * G8_STAGE;

__global__ void __launch_bounds__(256, 2) gemm8_kernel()
{
    extern __shared__ uint8_t sm8[];
    const uint32_t sb = s2u(sm8);

    const int tid  = threadIdx.x;
    const int lane = tid & 31;
    const int w    = tid >> 5;
    const int wm   = w & 3;
    const int wn   = w >> 2;
    const int col0 = blockIdx.x * 64;
    const int row0 = blockIdx.y * 128;
    const int z    = blockIdx.z;

    const int8_t* Ah8 = g_x8h;
    const int8_t* Al8 = g_x8l;
    const int8_t* Wh8 = g_w8h + (size_t)z * Dn * Dn;
    const int8_t* Wl8 = g_w8l + (size_t)z * Dn * Dn;

    int Chh[2][4][4], Cmd[2][4][4];
    #pragma unroll
    for (int mi = 0; mi < 2; mi++)
        #pragma unroll
        for (int ni = 0; ni < 4; ni++)
            #pragma unroll
            for (int q = 0; q < 4; q++) { Chh[mi][ni][q] = 0; Cmd[mi][ni][q] = 0; }

    auto issue = [&](int c_, int s_) {
        uint32_t dstb = sb + (uint32_t)s_ * G8_STAGE;
        int k0 = c_ * 64;
        #pragma unroll
        for (int i = 0; i < 4; i++) {          // A hi/lo
            int hil = i >> 1;
            int local = (i & 1) * 256 + tid;
            int r = local >> 2, cc = local & 3;
            uint32_t dst = dstb + hil * 10240u + (uint32_t)(r * 80 + cc * 16);
            const int8_t* src = (hil ? Al8 : Ah8)
                                + (size_t)(row0 + r) * Dn + k0 + cc * 16;
            cp16(dst, src);
        }
        #pragma unroll
        for (int i = 0; i < 2; i++) {          // B hi/lo
            int n = tid >> 2, cc = tid & 3;
            uint32_t dst = dstb + 20480u + i * 5120u
                           + (uint32_t)(n * 80 + cc * 16);
            const int8_t* src = (i ? Wl8 : Wh8)
                                + (size_t)(col0 + n) * Dn + k0 + cc * 16;
            cp16(dst, src);
        }
    };

    issue(0, 0); CP_COMMIT();
    issue(1, 1); CP_COMMIT();

    int st = 0;
    for (int c = 0; c < 16; c++) {
        if (c < 15) CP_WAIT1(); else CP_WAIT0();
        __syncthreads();
        if (c + 2 < 16) {
            int st2 = st + 2; if (st2 >= 3) st2 -= 3;
            issue(c + 2, st2);
            CP_COMMIT();
        }
        const uint32_t stgb = sb + (uint32_t)st * G8_STAGE;
        st = (st + 1 == 3) ? 0 : st + 1;

        #pragma unroll
        for (int ks = 0; ks < 2; ks++) {       // two k32 halves
            uint32_t ah[2][4], al[2][4], bh[4][2], bl[4][2];
            #pragma unroll
            for (int mi = 0; mi < 2; mi++) {
                uint32_t addr = stgb
                    + (uint32_t)((wm * 32 + mi * 16 + (lane & 15)) * 80
                                 + ks * 32 + ((lane >> 4) * 16));
                ldm_x4(ah[mi], addr);
                ldm_x4(al[mi], addr + 10240u);
            }
            #pragma unroll
            for (int g = 0; g < 2; g++) {
                uint32_t addr = stgb + 20480u
                    + (uint32_t)((wn * 32 + g * 16 + (lane & 7)
                                  + ((lane >> 4) << 3)) * 80
                                 + ((lane >> 3) & 1) * 16 + ks * 32);
                uint32_t t[4];
                ldm_x4(t, addr);
                bh[g*2][0] = t[0]; bh[g*2][1] = t[1];
                bh[g*2+1][0] = t[2]; bh[g*2+1][1] = t[3];
                ldm_x4(t, addr + 5120u);
                bl[g*2][0] = t[0]; bl[g*2][1] = t[1];
                bl[g*2+1][0] = t[2]; bl[g*2+1][1] = t[3];
            }
            #pragma unroll
            for (int mi = 0; mi < 2; mi++)
                #pragma unroll
                for (int ni = 0; ni < 4; ni++) {
                    mma_s8(Chh[mi][ni], ah[mi], bh[ni]);
                    mma_s8(Cmd[mi][ni], ah[mi], bl[ni]);
                    mma_s8(Cmd[mi][ni], al[mi], bh[ni]);
                }
        }
    }

    // Epilogue: reconstruct fp32, pack bf16 hi/lo into g_qkv (q scaled 0.125)
    const float s = (z == 0) ? 0.125f * INV8 : INV8;
    uint16_t* qh = g_qkvh + (size_t)z * PLANE;
    uint16_t* ql = g_qkvl + (size_t)z * PLANE;
    #pragma unroll
    for (int mi = 0; mi < 2; mi++)
        #pragma unroll
        for (int ni = 0; ni < 4; ni++) {
            int row = row0 + wm * 32 + mi * 16 + (lane >> 2);
            int col = col0 + wn * 32 + ni * 8 + (lane & 3) * 2;
            int hh = col >> 6, hd = col & 63;
            #pragma unroll
            for (int half = 0; half < 2; half++) {
                int r = row + half * 8;
                int b = r >> 11, l = r & 2047;
                size_t off = (((size_t)(b * Hn + hh) * Ln + l) << 6) + hd;
                float v0 = ((float)Chh[mi][ni][half*2]   * 16384.f
                            + (float)Cmd[mi][ni][half*2]   * 128.f) * s;
                float v1 = ((float)Chh[mi][ni][half*2+1] * 16384.f
                            + (float)Cmd[mi][ni][half*2+1] * 128.f) * s;
                uint32_t hw, lw;
                packhl(v0, v1, hw, lw);
                *(uint32_t*)(qh + off) = hw;
                *(uint32_t*)(ql + off) = lw;
            }
        }
}

// ---------------------------------------------------------------------------
// bf16-split out-projection GEMM (round-7 structure, Wo only)
// ---------------------------------------------------------------------------
constexpr int G_STAGE = 29696;
constexpr int GEMM_SMEM_BYTES = 3 * G_STAGE;

__global__ void __launch_bounds__(256, 2) gemmo_kernel(float* __restrict__ outp)
{
    extern __shared__ uint16_t smg[];
    const uint32_t sb = s2u(smg);

    const int tid  = threadIdx.x;
    const int lane = tid & 31;
    const int w    = tid >> 5;
    const int wm   = w & 3;
    const int wn   = w >> 2;
    const int col0 = blockIdx.x * 64;
    const int row0 = blockIdx.y * 128;

    float C[2][4][4];
    #pragma unroll
    for (int mi = 0; mi < 2; mi++)
        #pragma unroll
        for (int ni = 0; ni < 4; ni++)
            #pragma unroll
            for (int q = 0; q < 4; q++) C[mi][ni][q] = 0.f;

    auto issue = [&](int c_, int s_) {
        uint32_t dstb = sb + (uint32_t)s_ * G_STAGE;
        int k0 = c_ * 32;
        #pragma unroll
        for (int i = 0; i < 4; i++) {
            int hil = i >> 1;
            int local = (i & 1) * 256 + tid;
            int r = local >> 2, cc = local & 3;
            uint32_t dst = dstb + hil * 10240u + (uint32_t)(r * 40 + cc * 8) * 2;
            const uint16_t* src = (hil ? g_yl : g_yh)
                                  + (size_t)(row0 + r) * Dn + k0 + cc * 8;
            cp16(dst, src);
        }
        #pragma unroll
        for (int i = 0; i < 2; i++) {
            int kk = tid >> 3, cc = tid & 7;
            uint32_t dst = dstb + 20480u + i * 4608u
                           + (uint32_t)(kk * 72 + cc * 8) * 2;
            const uint16_t* src = (i ? g_wl : g_wh)
                                  + (size_t)(k0 + kk) * Dn + col0 + cc * 8;
            cp16(dst, src);
        }
    };

    issue(0, 0); CP_COMMIT();
    issue(1, 1); CP_COMMIT();

    int st = 0;
    for (int c = 0; c < 32; c++) {
        if (c < 31) CP_WAIT1(); else CP_WAIT0();
        __syncthreads();
        if (c + 2 < 32) {
            int st2 = st + 2; if (st2 >= 3) st2 -= 3;
            issue(c + 2, st2);
            CP_COMMIT();
        }
        const uint32_t stgb = sb + (uint32_t)st * G_STAGE;
        st = (st + 1 == 3) ? 0 : st + 1;

        #pragma unroll
        for (int ks = 0; ks < 2; ks++) {
            uint32_t ahf[2][4], alf[2][4], bhf[4][2], blf[4][2];
            #pragma unroll
            for (int mi = 0; mi < 2; mi++) {
                uint32_t off = (uint32_t)((wm * 32 + mi * 16 + (lane & 15)) * 80
                                          + ks * 32 + ((lane >> 4) * 16));
                ldm_x4(ahf[mi], stgb + off);
                ldm_x4(alf[mi], stgb + 10240u + off);
            }
            #pragma unroll
            for (int g = 0; g < 2; g++) {
                uint32_t off = 20480u
                    + (uint32_t)((ks * 16 + (lane & 15)) * 144
                                 + (wn * 32 + g * 16 + ((lane >> 4) * 8)) * 2);
                uint32_t t[4];
                ldm_x4t(t, stgb + off);
                bhf[g*2][0] = t[0]; bhf[g*2][1] = t[1];
                bhf[g*2+1][0] = t[2]; bhf[g*2+1][1] = t[3];
                ldm_x4t(t, stgb + 4608u + off);
                blf[g*2][0] = t[0]; blf[g*2][1] = t[1];
                blf[g*2+1][0] = t[2]; blf[g*2+1][1] = t[3];
            }
            #pragma unroll
            for (int mi = 0; mi < 2; mi++)
                #pragma unroll
                for (int ni = 0; ni < 4; ni++) {
                    mma_bf16(C[mi][ni], ahf[mi], bhf[ni]);
                    mma_bf16(C[mi][ni], ahf[mi], blf[ni]);
                    mma_bf16(C[mi][ni], alf[mi], bhf[ni]);
                }
        }
    }

    #pragma unroll
    for (int mi = 0; mi < 2; mi++)
        #pragma unroll
        for (int ni = 0; ni < 4; ni++) {
            int row = row0 + wm * 32 + mi * 16 + (lane >> 2);
            int col = col0 + wn * 32 + ni * 8 + (lane & 3) * 2;
            float2 v0 = make_float2(C[mi][ni][0], C[mi][ni][1]);
            float2 v1 = make_float2(C[mi][ni][2], C[mi][ni][3]);
            *(float2*)(outp + (size_t)row * Dn + col) = v0;
            *(float2*)(outp + (size_t)(row + 8) * Dn + col) = v1;
        }
}

// ---------------------------------------------------------------------------
// Tensor-core flash attention (unchanged from round 7)
// ---------------------------------------------------------------------------
constexpr int QS = 72;
constexpr int A_STAGE = 36864;
constexpr int ATTN_SMEM_BYTES = 3 * A_STAGE;   // 110,592

__global__ void __launch_bounds__(256) attn_kernel()
{
    extern __shared__ uint16_t smh[];
    const uint32_t sb = s2u(smh);

    const int qt   = blockIdx.x;
    const int h    = blockIdx.y;
    const int b    = blockIdx.z;
    const int tid  = threadIdx.x;
    const int lane = tid & 31;
    const int wid  = tid >> 5;
    const int r0   = wid * 16;

    const size_t base = ((size_t)(b * Hn + h) * Ln) * HDn;
    const uint16_t* qh_g = g_qkvh + base;
    const uint16_t* ql_g = g_qkvl + base;
    const uint16_t* kh_g = g_qkvh + PLANE + base;
    const uint16_t* kl_g = g_qkvl + PLANE + base;
    const uint16_t* vh_g = g_qkvh + 2 * PLANE + base;
    const uint16_t* vl_g = g_qkvl + 2 * PLANE + base;

    const int ktmax = 2 * qt + 2;

    auto issue_kv = [&](int kt_, int s_) {
        uint32_t dstb = sb + (uint32_t)s_ * A_STAGE;
        #pragma unroll
        for (int i = 0; i < 8; i++) {
            int p = i >> 1;
            int local = (i & 1) * 256 + tid;
            int r = local >> 3, cc = local & 7;
            uint32_t dst = dstb + p * 9216u + (uint32_t)(r * QS + cc * 8) * 2;
            const uint16_t* gp = (p == 0) ? kh_g : (p == 1) ? kl_g
                                : (p == 2) ? vh_g : vl_g;
            cp16(dst, gp + (size_t)(kt_ * 64 + r) * HDn + cc * 8);
        }
    };

    issue_kv(0, 0); CP_COMMIT();
    issue_kv(1, 1); CP_COMMIT();

    #pragma unroll
    for (int i = 0; i < 4; i++) {
        int idx = tid + i * 256;
        int r = idx >> 3, c8 = idx & 7;
        size_t go = (size_t)(qt * 128 + r) * HDn + c8 * 8;
        *(uint4*)(smh + 36864 + r * QS + c8 * 8) = *(const uint4*)(qh_g + go);
        *(uint4*)(smh + 46080 + r * QS + c8 * 8) = *(const uint4*)(ql_g + go);
    }
    __syncthreads();

    uint32_t qfh[4][4], qfl[4][4];
    #pragma unroll
    for (int ks = 0; ks < 4; ks++) {
        uint32_t qaddr = sb + (uint32_t)((36864 + (r0 + (lane & 15)) * QS
                          + ks * 16 + ((lane >> 4) * 8)) * 2);
        ldm_x4(qfh[ks], qaddr);
        ldm_x4(qfl[ks], qaddr + 9216u * 2);
    }

    float m0 = -1e30f, m1 = -1e30f, l0 = 0.f, l1 = 0.f;
    float O[8][4];
    #pragma unroll
    for (int nt = 0; nt < 8; nt++)
        #pragma unroll
        for (int q = 0; q < 4; q++) O[nt][q] = 0.f;

    const int qbase = qt * 128 + r0;

    int st = 0;
    for (int kt = 0; kt < ktmax; kt++) {
        if (kt + 1 < ktmax) CP_WAIT1(); else CP_WAIT0();
        __syncthreads();
        if (kt + 2 < ktmax) {
            int st2 = st + 2; if (st2 >= 3) st2 -= 3;
            issue_kv(kt + 2, st2);
            CP_COMMIT();
        }
        const uint32_t stgb = sb + (uint32_t)st * A_STAGE;
        st = (st + 1 == 3) ? 0 : st + 1;

        if (kt * 64 > qbase + 15) continue;

        float S[8][4];
        #pragma unroll
        for (int nt = 0; nt < 8; nt++)
            #pragma unroll
            for (int q = 0; q < 4; q++) S[nt][q] = 0.f;

        #pragma unroll
        for (int ks = 0; ks < 4; ks++) {
            #pragma unroll
            for (int ntp = 0; ntp < 4; ntp++) {
                uint32_t kaddr = stgb + (uint32_t)(((ntp * 16 + (lane & 7)
                                  + ((lane >> 4) << 3)) * QS
                                  + ((lane >> 3) & 1) * 8 + ks * 16) * 2);
                uint32_t bh[4], bl[4];
                ldm_x4(bh, kaddr);
                ldm_x4(bl, kaddr + 9216u);
                mma_bf16(S[2*ntp],   qfh[ks], bh);
                mma_bf16(S[2*ntp],   qfh[ks], bl);
                mma_bf16(S[2*ntp],   qfl[ks], bh);
                mma_bf16(S[2*ntp+1], qfh[ks], bh + 2);
                mma_bf16(S[2*ntp+1], qfh[ks], bl + 2);
                mma_bf16(S[2*ntp+1], qfl[ks], bh + 2);
            }
        }

        if (kt * 64 + 63 > qbase) {
            int q0 = qbase + (lane >> 2);
            int q1 = q0 + 8;
            #pragma unroll
            for (int nt = 0; nt < 8; nt++) {
                int k0 = kt * 64 + nt * 8 + (lane & 3) * 2;
                if (k0     > q0) S[nt][0] = -1e30f;
                if (k0 + 1 > q0) S[nt][1] = -1e30f;
                if (k0     > q1) S[nt][2] = -1e30f;
                if (k0 + 1 > q1) S[nt][3] = -1e30f;
            }
        }

        float mx0 = -1e30f, mx1 = -1e30f;
        #pragma unroll
        for (int nt = 0; nt < 8; nt++) {
            mx0 = fmaxf(mx0, fmaxf(S[nt][0], S[nt][1]));
            mx1 = fmaxf(mx1, fmaxf(S[nt][2], S[nt][3]));
        }
        mx0 = fmaxf(mx0, __shfl_xor_sync(0xffffffffu, mx0, 1));
        mx0 = fmaxf(mx0, __shfl_xor_sync(0xffffffffu, mx0, 2));
        mx1 = fmaxf(mx1, __shfl_xor_sync(0xffffffffu, mx1, 1));
        mx1 = fmaxf(mx1, __shfl_xor_sync(0xffffffffu, mx1, 2));
        float nm0 = fmaxf(m0, mx0), nm1 = fmaxf(m1, mx1);
        float c0 = __expf(m0 - nm0), c1 = __expf(m1 - nm1);
        float s0 = 0.f, s1 = 0.f;
        #pragma unroll
        for (int nt = 0; nt < 8; nt++) {
            S[nt][0] = __expf(S[nt][0] - nm0);
            S[nt][1] = __expf(S[nt][1] - nm0);
            S[nt][2] = __expf(S[nt][2] - nm1);
            S[nt][3] = __expf(S[nt][3] - nm1);
            s0 += S[nt][0] + S[nt][1];
            s1 += S[nt][2] + S[nt][3];
        }
        s0 += __shfl_xor_sync(0xffffffffu, s0, 1);
        s0 += __shfl_xor_sync(0xffffffffu, s0, 2);
        s1 += __shfl_xor_sync(0xffffffffu, s1, 1);
        s1 += __shfl_xor_sync(0xffffffffu, s1, 2);
        m0 = nm0; m1 = nm1;
        l0 = l0 * c0 + s0;
        l1 = l1 * c1 + s1;
        #pragma unroll
        for (int nt = 0; nt < 8; nt++) {
            O[nt][0] *= c0; O[nt][1] *= c0;
            O[nt][2] *= c1; O[nt][3] *= c1;
        }

        #pragma unroll
        for (int g = 0; g < 4; g++) {
            uint32_t ah[4], al[4];
            packhl(S[2*g][0],   S[2*g][1],   ah[0], al[0]);
            packhl(S[2*g][2],   S[2*g][3],   ah[1], al[1]);
            packhl(S[2*g+1][0], S[2*g+1][1], ah[2], al[2]);
            packhl(S[2*g+1][2], S[2*g+1][3], ah[3], al[3]);
            #pragma unroll
            for (int ntp = 0; ntp < 4; ntp++) {
                uint32_t vaddr = stgb + 18432u
                    + (uint32_t)(((g * 16 + (lane & 15)) * QS
                                  + ntp * 16 + ((lane >> 4) << 3)) * 2);
                uint32_t vh[4], vl[4];
                ldm_x4t(vh, vaddr);
                ldm_x4t(vl, vaddr + 9216u);
                mma_bf16(O[2*ntp],   ah, vh);
                mma_bf16(O[2*ntp],   ah, vl);
                mma_bf16(O[2*ntp],   al, vh);
                mma_bf16(O[2*ntp+1], ah, vh + 2);
                mma_bf16(O[2*ntp+1], ah, vl + 2);
                mma_bf16(O[2*ntp+1], al, vh + 2);
            }
        }
    }

    float il0 = 1.f / l0, il1 = 1.f / l1;
    int rowg = qt * 128 + r0 + (lane >> 2);
    #pragma unroll
    for (int nt = 0; nt < 8; nt++) {
        int hd = nt * 8 + (lane & 3) * 2;
        size_t o0 = (size_t)(b * Ln + rowg) * Dn + h * 64 + hd;
        size_t o1 = (size_t)(b * Ln + rowg + 8) * Dn + h * 64 + hd;
        uint32_t hw, lw;
        packhl(O[nt][0] * il0, O[nt][1] * il0, hw, lw);
        *(uint32_t*)(g_yh + o0) = hw;
        *(uint32_t*)(g_yl + o0) = lw;
        packhl(O[nt][2] * il1, O[nt][3] * il1, hw, lw);
        *(uint32_t*)(g_yh + o1) = hw;
        *(uint32_t*)(g_yl + o1) = lw;
    }
}

// ---------------------------------------------------------------------------
extern "C" void kernel_launch(void* const* d_in, const int* in_sizes, int n_in,
                              void* d_out, int out_size)
{
    (void)in_sizes; (void)n_in; (void)out_size;
    const float* x  = (const float*)d_in[0];
    const float* Wq = (const float*)d_in[1];
    const float* Wk = (const float*)d_in[2];
    const float* Wv = (const float*)d_in[3];
    const float* Wo = (const float*)d_in[4];
    float* out = (float*)d_out;

    cudaFuncSetAttribute(gemm8_kernel,
                         cudaFuncAttributeMaxDynamicSharedMemorySize, G8_SMEM);
    cudaFuncSetAttribute(gemmo_kernel,
                         cudaFuncAttributeMaxDynamicSharedMemorySize,
                         GEMM_SMEM_BYTES);
    cudaFuncSetAttribute(attn_kernel,
                         cudaFuncAttributeMaxDynamicSharedMemorySize,
                         ATTN_SMEM_BYTES);

    prep_kernel<<<5888, 256>>>(x, Wq, Wk, Wv, Wo);
    gemm8_kernel<<<dim3(Dn/64, NROW/128, 3), 256, G8_SMEM>>>();
    attn_kernel<<<dim3(Ln/128, Hn, Bn), 256, ATTN_SMEM_BYTES>>>();
    gemmo_kernel<<<dim3(Dn/64, NROW/128), 256, GEMM_SMEM_BYTES>>>(out);
}

// round 9
// speedup vs baseline: 3.0747x; 3.0747x over previous
#include <cuda_runtime.h>
#include <cuda_bf16.h>
#include <cuda_fp16.h>
#include <cstdint>

// Problem constants
constexpr int Bn  = 2;
constexpr int Ln  = 2048;
constexpr int Dn  = 1024;
constexpr int Hn  = 16;
constexpr int HDn = 64;
constexpr int NROW = Bn * Ln;   // 4096
constexpr size_t PLANE = (size_t)Bn * Hn * Ln * HDn;  // 4M elems

// Scaling to keep fp16 lo-planes out of subnormal range
constexpr float SC_X = 16.f;    // x stored as fp16(16x) hi/lo
constexpr float SC_W = 32.f;    // weights stored as fp16(32W)
constexpr float SC_Y = 256.f;   // attn output stored as fp16(256y) hi/lo
constexpr float INV_QKV = 1.f / (16.f * 32.f);    // 1/512
constexpr float INV_OUT = 1.f / (256.f * 32.f);   // 1/8192

// Scratch (device globals: allocation-free)
__device__ uint16_t g_xh[(size_t)NROW * Dn];      // fp16 hi of 16*x, [m][k]
__device__ uint16_t g_xl[(size_t)NROW * Dn];      // fp16 lo
__device__ uint16_t g_w16[(size_t)4 * Dn * Dn];   // fp16(32W): Wq,Wk,Wv,Wo [k][n]
__device__ uint16_t g_qkvh[3 * PLANE];            // bf16 hi, [3][B][H][L][HD]
__device__ uint16_t g_qkvl[3 * PLANE];            // bf16 lo
__device__ uint16_t g_yh[(size_t)NROW * Dn];      // fp16 hi of 256*y
__device__ uint16_t g_yl[(size_t)NROW * Dn];      // fp16 lo

// ---------------------------------------------------------------------------
// Helpers
// ---------------------------------------------------------------------------
__device__ __forceinline__ uint32_t s2u(const void* p) {
    uint32_t a;
    asm("{ .reg .u64 t; cvta.to.shared.u64 t, %1; cvt.u32.u64 %0, t; }"
        : "=r"(a) : "l"(p));
    return a;
}
__device__ __forceinline__ void cp16(uint32_t dst, const void* src) {
    asm volatile("cp.async.cg.shared.global [%0], [%1], 16;"
                 :: "r"(dst), "l"(src) : "memory");
}
#define CP_COMMIT() asm volatile("cp.async.commit_group;" ::: "memory")
#define CP_WAIT0()  asm volatile("cp.async.wait_group 0;" ::: "memory")

__device__ __forceinline__ void ldm_x4(uint32_t* r, uint32_t a) {
    asm volatile("ldmatrix.sync.aligned.m8n8.x4.shared.b16 {%0,%1,%2,%3}, [%4];"
                 : "=r"(r[0]), "=r"(r[1]), "=r"(r[2]), "=r"(r[3]) : "r"(a));
}
__device__ __forceinline__ void ldm_x4t(uint32_t* r, uint32_t a) {
    asm volatile("ldmatrix.sync.aligned.m8n8.x4.trans.shared.b16 {%0,%1,%2,%3}, [%4];"
                 : "=r"(r[0]), "=r"(r[1]), "=r"(r[2]), "=r"(r[3]) : "r"(a));
}
__device__ __forceinline__ void mma_bf16(float* c, const uint32_t* a,
                                         const uint32_t* b) {
    asm volatile(
        "mma.sync.aligned.m16n8k16.row.col.f32.bf16.bf16.f32 "
        "{%0,%1,%2,%3}, {%4,%5,%6,%7}, {%8,%9}, {%0,%1,%2,%3};"
        : "+f"(c[0]), "+f"(c[1]), "+f"(c[2]), "+f"(c[3])
        : "r"(a[0]), "r"(a[1]), "r"(a[2]), "r"(a[3]), "r"(b[0]), "r"(b[1]));
}
__device__ __forceinline__ void mma_f16(float* c, const uint32_t* a,
                                        const uint32_t* b) {
    asm volatile(
        "mma.sync.aligned.m16n8k16.row.col.f32.f16.f16.f32 "
        "{%0,%1,%2,%3}, {%4,%5,%6,%7}, {%8,%9}, {%0,%1,%2,%3};"
        : "+f"(c[0]), "+f"(c[1]), "+f"(c[2]), "+f"(c[3])
        : "r"(a[0]), "r"(a[1]), "r"(a[2]), "r"(a[3]), "r"(b[0]), "r"(b[1]));
}
// bf16 helpers (attention internals)
__device__ __forceinline__ uint16_t bfu(float f) {
    __nv_bfloat16 h = __float2bfloat16_rn(f);
    return *(uint16_t*)&h;
}
__device__ __forceinline__ float bff(uint16_t u) {
    __nv_bfloat16 h = *(__nv_bfloat16*)&u;
    return __bfloat162float(h);
}
__device__ __forceinline__ void packhl(float f0, float f1,
                                       uint32_t& h2, uint32_t& l2) {
    uint16_t h0 = bfu(f0), h1 = bfu(f1);
    uint16_t l0 = bfu(f0 - bff(h0)), l1 = bfu(f1 - bff(h1));
    h2 = (uint32_t)h0 | ((uint32_t)h1 << 16);
    l2 = (uint32_t)l0 | ((uint32_t)l1 << 16);
}
// fp16 helpers
__device__ __forceinline__ uint16_t hfu(float f) {
    __half h = __float2half_rn(f);
    return *(uint16_t*)&h;
}
__device__ __forceinline__ float hff(uint16_t u) {
    __half h = *(__half*)&u;
    return __half2float(h);
}
__device__ __forceinline__ void split4h(float4 v, uint2& hi, uint2& lo) {
    uint16_t h0 = hfu(v.x), h1 = hfu(v.y), h2 = hfu(v.z), h3 = hfu(v.w);
    uint16_t l0 = hfu(v.x - hff(h0)), l1 = hfu(v.y - hff(h1));
    uint16_t l2 = hfu(v.z - hff(h2)), l3 = hfu(v.w - hff(h3));
    hi = make_uint2((uint32_t)h0 | ((uint32_t)h1 << 16),
                    (uint32_t)h2 | ((uint32_t)h3 << 16));
    lo = make_uint2((uint32_t)l0 | ((uint32_t)l1 << 16),
                    (uint32_t)l2 | ((uint32_t)l3 << 16));
}
__device__ __forceinline__ uint2 pack4h(float4 v) {
    uint16_t h0 = hfu(v.x), h1 = hfu(v.y), h2 = hfu(v.z), h3 = hfu(v.w);
    return make_uint2((uint32_t)h0 | ((uint32_t)h1 << 16),
                      (uint32_t)h2 | ((uint32_t)h3 << 16));
}
__device__ __forceinline__ void packhl_h(float f0, float f1,
                                         uint32_t& h2, uint32_t& l2) {
    uint16_t h0 = hfu(f0), h1 = hfu(f1);
    uint16_t l0 = hfu(f0 - hff(h0)), l1 = hfu(f1 - hff(h1));
    h2 = (uint32_t)h0 | ((uint32_t)h1 << 16);
    l2 = (uint32_t)l0 | ((uint32_t)l1 << 16);
}

// ---------------------------------------------------------------------------
// Prep: x -> fp16(16x) hi/lo [m][k]; all 4 weights -> fp16(32W) single [k][n].
// Grid: blocks [0,4096) handle x (1 float4/thread); [4096,8192) handle W.
// ---------------------------------------------------------------------------
__global__ void __launch_bounds__(256) prep_kernel(
    const float* __restrict__ x,
    const float* __restrict__ Wq, const float* __restrict__ Wk,
    const float* __restrict__ Wv, const float* __restrict__ Wo)
{
    int i = blockIdx.x * 256 + threadIdx.x;   // float4 index
    if (i < (1 << 20)) {
        float4 v = ((const float4*)x)[i];
        v.x *= SC_X; v.y *= SC_X; v.z *= SC_X; v.w *= SC_X;
        uint2 hi, lo;
        split4h(v, hi, lo);
        ((uint2*)g_xh)[i] = hi;
        ((uint2*)g_xl)[i] = lo;
    } else {
        int j = i - (1 << 20);
        int slot = j >> 18;                    // 0..3 = Wq,Wk,Wv,Wo
        int off  = j & ((1 << 18) - 1);
        const float* w = (slot == 0) ? Wq : (slot == 1) ? Wk
                        : (slot == 2) ? Wv : Wo;
        float4 v = ((const float4*)w)[off];
        v.x *= SC_W; v.y *= SC_W; v.z *= SC_W; v.w *= SC_W;
        ((uint2*)g_w16)[((size_t)slot << 18) + off] = pack4h(v);
    }
}

// ---------------------------------------------------------------------------
// fp16 2-pass GEMM: 128x64 CTA tile, 8 warps (4m x 2n), warp tile 32x32.
// A = hi/lo fp16 [m][k] (exact), B = single fp16 [k][n]. C = (Ah + Al) * B.
// 2-stage cp.async (round-6 pattern: wait0 + one barrier per iteration).
// Stage: Ah 0 (10240 B), Al 10240, B 20480 (4608 B). Stage 25088 B x2.
// mode 0: A = x, B slot z in {0,1,2}, C -> g_qkv bf16 hi/lo (z=0 scaled 1/8)
// mode 1: A = y,  B slot 3 (Wo),      C -> outp fp32
// ---------------------------------------------------------------------------
constexpr int G_STAGE = 25088;
constexpr int GEMM_SMEM_BYTES = 2 * G_STAGE;   // 50176

__global__ void __launch_bounds__(256, 2) gemm_mma_kernel(
    float* __restrict__ outp, int mode)
{
    extern __shared__ uint16_t smg[];
    const uint32_t sb = s2u(smg);

    const int tid  = threadIdx.x;
    const int lane = tid & 31;
    const int w    = tid >> 5;
    const int wm   = w & 3;         // 4 m-groups of 32
    const int wn   = w >> 2;        // 2 n-groups of 32
    const int col0 = blockIdx.x * 64;
    const int row0 = blockIdx.y * 128;
    const int z    = blockIdx.z;

    const uint16_t* Aph = (mode == 0) ? g_xh : g_yh;
    const uint16_t* Apl = (mode == 0) ? g_xl : g_yl;
    const int slot = (mode == 0) ? z : 3;
    const uint16_t* Bp = g_w16 + ((size_t)slot << 20);

    float C[2][4][4];
    #pragma unroll
    for (int mi = 0; mi < 2; mi++)
        #pragma unroll
        for (int ni = 0; ni < 4; ni++)
            #pragma unroll
            for (int q = 0; q < 4; q++) C[mi][ni][q] = 0.f;

    auto issue = [&](int c_, int s_) {
        uint32_t dstb = sb + (uint32_t)s_ * G_STAGE;
        int k0 = c_ * 32;
        #pragma unroll
        for (int i = 0; i < 4; i++) {          // A hi (2) + A lo (2)
            int hil = i >> 1;
            int local = (i & 1) * 256 + tid;
            int r = local >> 2, cc = local & 3;
            uint32_t dst = dstb + hil * 10240u + (uint32_t)(r * 40 + cc * 8) * 2;
            const uint16_t* src = (hil ? Apl : Aph)
                                  + (size_t)(row0 + r) * Dn + k0 + cc * 8;
            cp16(dst, src);
        }
        {                                      // B single (1)
            int kk = tid >> 3, cc = tid & 7;
            uint32_t dst = dstb + 20480u + (uint32_t)(kk * 72 + cc * 8) * 2;
            const uint16_t* src = Bp + (size_t)(k0 + kk) * Dn + col0 + cc * 8;
            cp16(dst, src);
        }
    };

    issue(0, 0);
    CP_COMMIT();

    for (int c = 0; c < 32; c++) {
        CP_WAIT0();
        __syncthreads();
        if (c + 1 < 32) {
            issue(c + 1, (c + 1) & 1);
            CP_COMMIT();
        }
        const uint32_t stgb = sb + (uint32_t)(c & 1) * G_STAGE;

        #pragma unroll
        for (int ks = 0; ks < 2; ks++) {
            uint32_t ahf[2][4], alf[2][4], bf[4][2];
            #pragma unroll
            for (int mi = 0; mi < 2; mi++) {
                uint32_t off = (uint32_t)((wm * 32 + mi * 16 + (lane & 15)) * 80
                                          + ks * 32 + ((lane >> 4) * 16));
                ldm_x4(ahf[mi], stgb + off);
                ldm_x4(alf[mi], stgb + 10240u + off);
            }
            #pragma unroll
            for (int g = 0; g < 2; g++) {
                uint32_t off = 20480u
                    + (uint32_t)((ks * 16 + (lane & 15)) * 144
                                 + (wn * 32 + g * 16 + ((lane >> 4) * 8)) * 2);
                uint32_t t[4];
                ldm_x4t(t, stgb + off);
                bf[g*2][0]   = t[0]; bf[g*2][1]   = t[1];
                bf[g*2+1][0] = t[2]; bf[g*2+1][1] = t[3];
            }
            #pragma unroll
            for (int mi = 0; mi < 2; mi++)
                #pragma unroll
                for (int ni = 0; ni < 4; ni++) {
                    mma_f16(C[mi][ni], ahf[mi], bf[ni]);
                    mma_f16(C[mi][ni], alf[mi], bf[ni]);
                }
        }
    }

    if (mode == 0) {
        const float s = INV_QKV * ((z == 0) ? 0.125f : 1.f);
        uint16_t* qh = g_qkvh + (size_t)z * PLANE;
        uint16_t* ql = g_qkvl + (size_t)z * PLANE;
        #pragma unroll
        for (int mi = 0; mi < 2; mi++)
            #pragma unroll
            for (int ni = 0; ni < 4; ni++) {
                int row = row0 + wm * 32 + mi * 16 + (lane >> 2);
                int col = col0 + wn * 32 + ni * 8 + (lane & 3) * 2;
                int hh = col >> 6, hd = col & 63;
                #pragma unroll
                for (int half = 0; half < 2; half++) {
                    int r = row + half * 8;
                    int b = r >> 11, l = r & 2047;
                    size_t off = (((size_t)(b * Hn + hh) * Ln + l) << 6) + hd;
                    uint32_t hw, lw;
                    packhl(C[mi][ni][half*2] * s, C[mi][ni][half*2+1] * s, hw, lw);
                    *(uint32_t*)(qh + off) = hw;
                    *(uint32_t*)(ql + off) = lw;
                }
            }
    } else {
        #pragma unroll
        for (int mi = 0; mi < 2; mi++)
            #pragma unroll
            for (int ni = 0; ni < 4; ni++) {
                int row = row0 + wm * 32 + mi * 16 + (lane >> 2);
                int col = col0 + wn * 32 + ni * 8 + (lane & 3) * 2;
                float2 v0 = make_float2(C[mi][ni][0] * INV_OUT,
                                        C[mi][ni][1] * INV_OUT);
                float2 v1 = make_float2(C[mi][ni][2] * INV_OUT,
                                        C[mi][ni][3] * INV_OUT);
                *(float2*)(outp + (size_t)row * Dn + col) = v0;
                *(float2*)(outp + (size_t)(row + 8) * Dn + col) = v1;
            }
    }
}

// ---------------------------------------------------------------------------
// Tensor-core flash attention (round-6 structure, bf16 3-pass internals).
// Q frags register-resident; KV double-buffered via cp.async; Q staged in
// stage-1 region before the loop. Epilogue writes y as fp16(256y) hi/lo.
// Stage (bytes): KH 0 (9216), KL 9216, VH 18432, VL 27648; size 36864.
// ---------------------------------------------------------------------------
constexpr int QS = 72;                 // elems per row
constexpr int A_STAGE = 36864;         // bytes
constexpr int ATTN_SMEM_BYTES = 2 * A_STAGE;   // 73,728

__global__ void __launch_bounds__(256) attn_kernel()
{
    extern __shared__ uint16_t smh[];
    const uint32_t sb = s2u(smh);

    const int qt   = blockIdx.x;
    const int h    = blockIdx.y;
    const int b    = blockIdx.z;
    const int tid  = threadIdx.x;
    const int lane = tid & 31;
    const int wid  = tid >> 5;
    const int r0   = wid * 16;

    const size_t base = ((size_t)(b * Hn + h) * Ln) * HDn;
    const uint16_t* qh_g = g_qkvh + base;
    const uint16_t* ql_g = g_qkvl + base;
    const uint16_t* kh_g = g_qkvh + PLANE + base;
    const uint16_t* kl_g = g_qkvl + PLANE + base;
    const uint16_t* vh_g = g_qkvh + 2 * PLANE + base;
    const uint16_t* vl_g = g_qkvl + 2 * PLANE + base;

    // Load Q tile [128][64] hi/lo into stage-1 region (elems 18432 / 27648)
    #pragma unroll
    for (int i = 0; i < 4; i++) {
        int idx = tid + i * 256;
        int r = idx >> 3, c8 = idx & 7;
        size_t go = (size_t)(qt * 128 + r) * HDn + c8 * 8;
        *(uint4*)(smh + 18432 + r * QS + c8 * 8) = *(const uint4*)(qh_g + go);
        *(uint4*)(smh + 27648 + r * QS + c8 * 8) = *(const uint4*)(ql_g + go);
    }

    const int ktmax = 2 * qt + 2;

    auto issue_kv = [&](int kt_, int s_) {
        uint32_t dstb = sb + s_ * A_STAGE;
        #pragma unroll
        for (int i = 0; i < 8; i++) {
            int p = i >> 1;
            int local = (i & 1) * 256 + tid;
            int r = local >> 3, cc = local & 7;
            uint32_t dst = dstb + p * 9216u + (uint32_t)(r * QS + cc * 8) * 2;
            const uint16_t* gp = (p == 0) ? kh_g : (p == 1) ? kl_g
                                : (p == 2) ? vh_g : vl_g;
            cp16(dst, gp + (size_t)(kt_ * 64 + r) * HDn + cc * 8);
        }
    };
    issue_kv(0, 0);
    CP_COMMIT();
    __syncthreads();

    // Extract Q fragments to registers (reused every kt iteration)
    uint32_t qfh[4][4], qfl[4][4];
    #pragma unroll
    for (int ks = 0; ks < 4; ks++) {
        uint32_t qaddr = sb + (uint32_t)((18432 + (r0 + (lane & 15)) * QS
                          + ks * 16 + ((lane >> 4) * 8)) * 2);
        ldm_x4(qfh[ks], qaddr);
        ldm_x4(qfl[ks], qaddr + 9216u * 2);
    }
    __syncthreads();   // Q consumed; stage-1 region may be overwritten

    float m0 = -1e30f, m1 = -1e30f, l0 = 0.f, l1 = 0.f;
    float O[8][4];
    #pragma unroll
    for (int nt = 0; nt < 8; nt++)
        #pragma unroll
        for (int q = 0; q < 4; q++) O[nt][q] = 0.f;

    const int qbase = qt * 128 + r0;

    for (int kt = 0; kt < ktmax; kt++) {
        CP_WAIT0();
        __syncthreads();
        if (kt + 1 < ktmax) {
            issue_kv(kt + 1, (kt + 1) & 1);
            CP_COMMIT();
        }

        if (kt * 64 > qbase + 15) continue;

        const uint32_t stgb = sb + (kt & 1) * A_STAGE;

        // ---- S = Q * K^T (3-pass split) ----
        float S[8][4];
        #pragma unroll
        for (int nt = 0; nt < 8; nt++)
            #pragma unroll
            for (int q = 0; q < 4; q++) S[nt][q] = 0.f;

        #pragma unroll
        for (int ks = 0; ks < 4; ks++) {
            #pragma unroll
            for (int ntp = 0; ntp < 4; ntp++) {
                uint32_t kaddr = stgb + (uint32_t)(((ntp * 16 + (lane & 7)
                                  + ((lane >> 4) << 3)) * QS
                                  + ((lane >> 3) & 1) * 8 + ks * 16) * 2);
                uint32_t bh[4], bl[4];
                ldm_x4(bh, kaddr);            // KH
                ldm_x4(bl, kaddr + 9216u);    // KL
                mma_bf16(S[2*ntp],   qfh[ks], bh);
                mma_bf16(S[2*ntp],   qfh[ks], bl);
                mma_bf16(S[2*ntp],   qfl[ks], bh);
                mma_bf16(S[2*ntp+1], qfh[ks], bh + 2);
                mma_bf16(S[2*ntp+1], qfh[ks], bl + 2);
                mma_bf16(S[2*ntp+1], qfl[ks], bh + 2);
            }
        }

        // ---- causal mask (diagonal tiles only) ----
        if (kt * 64 + 63 > qbase) {
            int q0 = qbase + (lane >> 2);
            int q1 = q0 + 8;
            #pragma unroll
            for (int nt = 0; nt < 8; nt++) {
                int k0 = kt * 64 + nt * 8 + (lane & 3) * 2;
                if (k0     > q0) S[nt][0] = -1e30f;
                if (k0 + 1 > q0) S[nt][1] = -1e30f;
                if (k0     > q1) S[nt][2] = -1e30f;
                if (k0 + 1 > q1) S[nt][3] = -1e30f;
            }
        }

        // ---- online softmax ----
        float mx0 = -1e30f, mx1 = -1e30f;
        #pragma unroll
        for (int nt = 0; nt < 8; nt++) {
            mx0 = fmaxf(mx0, fmaxf(S[nt][0], S[nt][1]));
            mx1 = fmaxf(mx1, fmaxf(S[nt][2], S[nt][3]));
        }
        mx0 = fmaxf(mx0, __shfl_xor_sync(0xffffffffu, mx0, 1));
        mx0 = fmaxf(mx0, __shfl_xor_sync(0xffffffffu, mx0, 2));
        mx1 = fmaxf(mx1, __shfl_xor_sync(0xffffffffu, mx1, 1));
        mx1 = fmaxf(mx1, __shfl_xor_sync(0xffffffffu, mx1, 2));
        float nm0 = fmaxf(m0, mx0), nm1 = fmaxf(m1, mx1);
        float c0 = __expf(m0 - nm0), c1 = __expf(m1 - nm1);
        float s0 = 0.f, s1 = 0.f;
        #pragma unroll
        for (int nt = 0; nt < 8; nt++) {
            S[nt][0] = __expf(S[nt][0] - nm0);
            S[nt][1] = __expf(S[nt][1] - nm0);
            S[nt][2] = __expf(S[nt][2] - nm1);
            S[nt][3] = __expf(S[nt][3] - nm1);
            s0 += S[nt][0] + S[nt][1];
            s1 += S[nt][2] + S[nt][3];
        }
        s0 += __shfl_xor_sync(0xffffffffu, s0, 1);
        s0 += __shfl_xor_sync(0xffffffffu, s0, 2);
        s1 += __shfl_xor_sync(0xffffffffu, s1, 1);
        s1 += __shfl_xor_sync(0xffffffffu, s1, 2);
        m0 = nm0; m1 = nm1;
        l0 = l0 * c0 + s0;
        l1 = l1 * c1 + s1;
        #pragma unroll
        for (int nt = 0; nt < 8; nt++) {
            O[nt][0] *= c0; O[nt][1] *= c0;
            O[nt][2] *= c1; O[nt][3] *= c1;
        }

        // ---- O += P * V (3-pass split) ----
        #pragma unroll
        for (int g = 0; g < 4; g++) {
            uint32_t ah[4], al[4];
            packhl(S[2*g][0],   S[2*g][1],   ah[0], al[0]);
            packhl(S[2*g][2],   S[2*g][3],   ah[1], al[1]);
            packhl(S[2*g+1][0], S[2*g+1][1], ah[2], al[2]);
            packhl(S[2*g+1][2], S[2*g+1][3], ah[3], al[3]);
            #pragma unroll
            for (int ntp = 0; ntp < 4; ntp++) {
                uint32_t vaddr = stgb + 18432u
                    + (uint32_t)(((g * 16 + (lane & 15)) * QS
                                  + ntp * 16 + ((lane >> 4) << 3)) * 2);
                uint32_t vh[4], vl[4];
                ldm_x4t(vh, vaddr);            // VH
                ldm_x4t(vl, vaddr + 9216u);    // VL
                mma_bf16(O[2*ntp],   ah, vh);
                mma_bf16(O[2*ntp],   ah, vl);
                mma_bf16(O[2*ntp],   al, vh);
                mma_bf16(O[2*ntp+1], ah, vh + 2);
                mma_bf16(O[2*ntp+1], ah, vl + 2);
                mma_bf16(O[2*ntp+1], al, vh + 2);
            }
        }
    }

    // Finalize: scale by SC_Y/l and store y as fp16 hi/lo for out-proj
    float il0 = SC_Y / l0, il1 = SC_Y / l1;
    int rowg = qt * 128 + r0 + (lane >> 2);
    #pragma unroll
    for (int nt = 0; nt < 8; nt++) {
        int hd = nt * 8 + (lane & 3) * 2;
        size_t o0 = (size_t)(b * Ln + rowg) * Dn + h * 64 + hd;
        size_t o1 = (size_t)(b * Ln + rowg + 8) * Dn + h * 64 + hd;
        uint32_t hw, lw;
        packhl_h(O[nt][0] * il0, O[nt][1] * il0, hw, lw);
        *(uint32_t*)(g_yh + o0) = hw;
        *(uint32_t*)(g_yl + o0) = lw;
        packhl_h(O[nt][2] * il1, O[nt][3] * il1, hw, lw);
        *(uint32_t*)(g_yh + o1) = hw;
        *(uint32_t*)(g_yl + o1) = lw;
    }
}

// ---------------------------------------------------------------------------
extern "C" void kernel_launch(void* const* d_in, const int* in_sizes, int n_in,
                              void* d_out, int out_size)
{
    (void)in_sizes; (void)n_in; (void)out_size;
    const float* x  = (const float*)d_in[0];
    const float* Wq = (const float*)d_in[1];
    const float* Wk = (const float*)d_in[2];
    const float* Wv = (const float*)d_in[3];
    const float* Wo = (const float*)d_in[4];
    float* out = (float*)d_out;

    cudaFuncSetAttribute(gemm_mma_kernel,
                         cudaFuncAttributeMaxDynamicSharedMemorySize,
                         GEMM_SMEM_BYTES);
    cudaFuncSetAttribute(attn_kernel,
                         cudaFuncAttributeMaxDynamicSharedMemorySize,
                         ATTN_SMEM_BYTES);

    prep_kernel<<<8192, 256>>>(x, Wq, Wk, Wv, Wo);
    gemm_mma_kernel<<<dim3(Dn/64, NROW/128, 3), 256, GEMM_SMEM_BYTES>>>(nullptr, 0);
    attn_kernel<<<dim3(Ln/128, Hn, Bn), 256, ATTN_SMEM_BYTES>>>();
    gemm_mma_kernel<<<dim3(Dn/64, NROW/128, 1), 256, GEMM_SMEM_BYTES>>>(out, 1);
}

// round 10
// speedup vs baseline: 3.2262x; 1.0493x over previous
#include <cuda_runtime.h>
#include <cuda_bf16.h>
#include <cuda_fp16.h>
#include <cstdint>

// Problem constants
constexpr int Bn  = 2;
constexpr int Ln  = 2048;
constexpr int Dn  = 1024;
constexpr int Hn  = 16;
constexpr int HDn = 64;
constexpr int NROW = Bn * Ln;   // 4096
constexpr size_t PLANE = (size_t)Bn * Hn * Ln * HDn;  // 4M elems

// Scaling
constexpr float SC_X = 16.f;    // x stored as fp16(16x) hi/lo
constexpr float SC_W = 32.f;    // weights stored as fp16(32W)
constexpr float SC_Y = 256.f;   // attn output stored as fp16(256y) hi/lo
constexpr float INV_QKV = 1.f / (16.f * 32.f);    // 1/512
constexpr float INV_OUT = 1.f / (256.f * 32.f);   // 1/8192

// Scratch (device globals: allocation-free)
__device__ uint16_t g_xh[(size_t)NROW * Dn];      // fp16 hi of 16*x, [m][k]
__device__ uint16_t g_xl[(size_t)NROW * Dn];      // fp16 lo
__device__ uint16_t g_w16[(size_t)4 * Dn * Dn];   // fp16(32W): Wq,Wk,Wv,Wo [k][n]
__device__ uint16_t g_qh[PLANE];                  // fp16 hi of 0.5*q, [B,H,L,HD]
__device__ uint16_t g_ql[PLANE];                  // fp16 lo
__device__ uint16_t g_k16[PLANE];                 // fp16 of 0.25*k
__device__ uint16_t g_v16[PLANE];                 // fp16 of v
__device__ uint16_t g_yh[(size_t)NROW * Dn];      // fp16 hi of 256*y
__device__ uint16_t g_yl[(size_t)NROW * Dn];      // fp16 lo

// ---------------------------------------------------------------------------
// Helpers
// ---------------------------------------------------------------------------
__device__ __forceinline__ uint32_t s2u(const void* p) {
    uint32_t a;
    asm("{ .reg .u64 t; cvta.to.shared.u64 t, %1; cvt.u32.u64 %0, t; }"
        : "=r"(a) : "l"(p));
    return a;
}
__device__ __forceinline__ void cp16(uint32_t dst, const void* src) {
    asm volatile("cp.async.cg.shared.global [%0], [%1], 16;"
                 :: "r"(dst), "l"(src) : "memory");
}
#define CP_COMMIT() asm volatile("cp.async.commit_group;" ::: "memory")
#define CP_WAIT0()  asm volatile("cp.async.wait_group 0;" ::: "memory")

__device__ __forceinline__ void ldm_x4(uint32_t* r, uint32_t a) {
    asm volatile("ldmatrix.sync.aligned.m8n8.x4.shared.b16 {%0,%1,%2,%3}, [%4];"
                 : "=r"(r[0]), "=r"(r[1]), "=r"(r[2]), "=r"(r[3]) : "r"(a));
}
__device__ __forceinline__ void ldm_x4t(uint32_t* r, uint32_t a) {
    asm volatile("ldmatrix.sync.aligned.m8n8.x4.trans.shared.b16 {%0,%1,%2,%3}, [%4];"
                 : "=r"(r[0]), "=r"(r[1]), "=r"(r[2]), "=r"(r[3]) : "r"(a));
}
__device__ __forceinline__ void mma_f16(float* c, const uint32_t* a,
                                        const uint32_t* b) {
    asm volatile(
        "mma.sync.aligned.m16n8k16.row.col.f32.f16.f16.f32 "
        "{%0,%1,%2,%3}, {%4,%5,%6,%7}, {%8,%9}, {%0,%1,%2,%3};"
        : "+f"(c[0]), "+f"(c[1]), "+f"(c[2]), "+f"(c[3])
        : "r"(a[0]), "r"(a[1]), "r"(a[2]), "r"(a[3]), "r"(b[0]), "r"(b[1]));
}
// fp16 helpers
__device__ __forceinline__ uint16_t hfu(float f) {
    __half h = __float2half_rn(f);
    return *(uint16_t*)&h;
}
__device__ __forceinline__ float hff(uint16_t u) {
    __half h = *(__half*)&u;
    return __half2float(h);
}
__device__ __forceinline__ void split4h(float4 v, uint2& hi, uint2& lo) {
    uint16_t h0 = hfu(v.x), h1 = hfu(v.y), h2 = hfu(v.z), h3 = hfu(v.w);
    uint16_t l0 = hfu(v.x - hff(h0)), l1 = hfu(v.y - hff(h1));
    uint16_t l2 = hfu(v.z - hff(h2)), l3 = hfu(v.w - hff(h3));
    hi = make_uint2((uint32_t)h0 | ((uint32_t)h1 << 16),
                    (uint32_t)h2 | ((uint32_t)h3 << 16));
    lo = make_uint2((uint32_t)l0 | ((uint32_t)l1 << 16),
                    (uint32_t)l2 | ((uint32_t)l3 << 16));
}
__device__ __forceinline__ uint2 pack4h(float4 v) {
    uint16_t h0 = hfu(v.x), h1 = hfu(v.y), h2 = hfu(v.z), h3 = hfu(v.w);
    return make_uint2((uint32_t)h0 | ((uint32_t)h1 << 16),
                      (uint32_t)h2 | ((uint32_t)h3 << 16));
}
__device__ __forceinline__ void packhl_h(float f0, float f1,
                                         uint32_t& h2, uint32_t& l2) {
    uint16_t h0 = hfu(f0), h1 = hfu(f1);
    uint16_t l0 = hfu(f0 - hff(h0)), l1 = hfu(f1 - hff(h1));
    h2 = (uint32_t)h0 | ((uint32_t)h1 << 16);
    l2 = (uint32_t)l0 | ((uint32_t)l1 << 16);
}
__device__ __forceinline__ uint32_t pack2h(float f0, float f1) {
    return (uint32_t)hfu(f0) | ((uint32_t)hfu(f1) << 16);
}

// ---------------------------------------------------------------------------
// Prep: x -> fp16(16x) hi/lo [m][k]; all 4 weights -> fp16(32W) single [k][n].
// ---------------------------------------------------------------------------
__global__ void __launch_bounds__(256) prep_kernel(
    const float* __restrict__ x,
    const float* __restrict__ Wq, const float* __restrict__ Wk,
    const float* __restrict__ Wv, const float* __restrict__ Wo)
{
    int i = blockIdx.x * 256 + threadIdx.x;   // float4 index
    if (i < (1 << 20)) {
        float4 v = ((const float4*)x)[i];
        v.x *= SC_X; v.y *= SC_X; v.z *= SC_X; v.w *= SC_X;
        uint2 hi, lo;
        split4h(v, hi, lo);
        ((uint2*)g_xh)[i] = hi;
        ((uint2*)g_xl)[i] = lo;
    } else {
        int j = i - (1 << 20);
        int slot = j >> 18;                    // 0..3 = Wq,Wk,Wv,Wo
        int off  = j & ((1 << 18) - 1);
        const float* w = (slot == 0) ? Wq : (slot == 1) ? Wk
                        : (slot == 2) ? Wv : Wo;
        float4 v = ((const float4*)w)[off];
        v.x *= SC_W; v.y *= SC_W; v.z *= SC_W; v.w *= SC_W;
        ((uint2*)g_w16)[((size_t)slot << 18) + off] = pack4h(v);
    }
}

// ---------------------------------------------------------------------------
// fp16 2-pass GEMM: 128x64 CTA tile, 8 warps (4m x 2n), warp tile 32x32.
// A = hi/lo fp16 [m][k] (exact), B = single fp16 [k][n]. C = (Ah + Al) * B.
// 2-stage cp.async. Stage: Ah 0 (10240 B), Al 10240, B 20480 (4608 B).
// mode 0: A = x; z=0 -> Q fp16 hi/lo (x0.5 w/ softmax scale), z=1 -> K fp16
//         single (x0.25), z=2 -> V fp16 single.  mode 1: A = y, Wo -> fp32 out.
// ---------------------------------------------------------------------------
constexpr int G_STAGE = 25088;
constexpr int GEMM_SMEM_BYTES = 2 * G_STAGE;   // 50176

__global__ void __launch_bounds__(256, 2) gemm_mma_kernel(
    float* __restrict__ outp, int mode)
{
    extern __shared__ uint16_t smg[];
    const uint32_t sb = s2u(smg);

    const int tid  = threadIdx.x;
    const int lane = tid & 31;
    const int w    = tid >> 5;
    const int wm   = w & 3;
    const int wn   = w >> 2;
    const int col0 = blockIdx.x * 64;
    const int row0 = blockIdx.y * 128;
    const int z    = blockIdx.z;

    const uint16_t* Aph = (mode == 0) ? g_xh : g_yh;
    const uint16_t* Apl = (mode == 0) ? g_xl : g_yl;
    const int slot = (mode == 0) ? z : 3;
    const uint16_t* Bp = g_w16 + ((size_t)slot << 20);

    float C[2][4][4];
    #pragma unroll
    for (int mi = 0; mi < 2; mi++)
        #pragma unroll
        for (int ni = 0; ni < 4; ni++)
            #pragma unroll
            for (int q = 0; q < 4; q++) C[mi][ni][q] = 0.f;

    auto issue = [&](int c_, int s_) {
        uint32_t dstb = sb + (uint32_t)s_ * G_STAGE;
        int k0 = c_ * 32;
        #pragma unroll
        for (int i = 0; i < 4; i++) {
            int hil = i >> 1;
            int local = (i & 1) * 256 + tid;
            int r = local >> 2, cc = local & 3;
            uint32_t dst = dstb + hil * 10240u + (uint32_t)(r * 40 + cc * 8) * 2;
            const uint16_t* src = (hil ? Apl : Aph)
                                  + (size_t)(row0 + r) * Dn + k0 + cc * 8;
            cp16(dst, src);
        }
        {
            int kk = tid >> 3, cc = tid & 7;
            uint32_t dst = dstb + 20480u + (uint32_t)(kk * 72 + cc * 8) * 2;
            const uint16_t* src = Bp + (size_t)(k0 + kk) * Dn + col0 + cc * 8;
            cp16(dst, src);
        }
    };

    issue(0, 0);
    CP_COMMIT();

    for (int c = 0; c < 32; c++) {
        CP_WAIT0();
        __syncthreads();
        if (c + 1 < 32) {
            issue(c + 1, (c + 1) & 1);
            CP_COMMIT();
        }
        const uint32_t stgb = sb + (uint32_t)(c & 1) * G_STAGE;

        #pragma unroll
        for (int ks = 0; ks < 2; ks++) {
            uint32_t ahf[2][4], alf[2][4], bf[4][2];
            #pragma unroll
            for (int mi = 0; mi < 2; mi++) {
                uint32_t off = (uint32_t)((wm * 32 + mi * 16 + (lane & 15)) * 80
                                          + ks * 32 + ((lane >> 4) * 16));
                ldm_x4(ahf[mi], stgb + off);
                ldm_x4(alf[mi], stgb + 10240u + off);
            }
            #pragma unroll
            for (int g = 0; g < 2; g++) {
                uint32_t off = 20480u
                    + (uint32_t)((ks * 16 + (lane & 15)) * 144
                                 + (wn * 32 + g * 16 + ((lane >> 4) * 8)) * 2);
                uint32_t t[4];
                ldm_x4t(t, stgb + off);
                bf[g*2][0]   = t[0]; bf[g*2][1]   = t[1];
                bf[g*2+1][0] = t[2]; bf[g*2+1][1] = t[3];
            }
            #pragma unroll
            for (int mi = 0; mi < 2; mi++)
                #pragma unroll
                for (int ni = 0; ni < 4; ni++) {
                    mma_f16(C[mi][ni], ahf[mi], bf[ni]);
                    mma_f16(C[mi][ni], alf[mi], bf[ni]);
                }
        }
    }

    if (mode == 0) {
        // z=0: Q stored as fp16 hi/lo of 0.5*q (0.5*0.25 = softmax 0.125 w/ K)
        // z=1: K stored single fp16 of 0.25*k ;  z=2: V stored single fp16
        const float s = INV_QKV * ((z == 0) ? 0.5f : (z == 1) ? 0.25f : 1.f);
        #pragma unroll
        for (int mi = 0; mi < 2; mi++)
            #pragma unroll
            for (int ni = 0; ni < 4; ni++) {
                int row = row0 + wm * 32 + mi * 16 + (lane >> 2);
                int col = col0 + wn * 32 + ni * 8 + (lane & 3) * 2;
                int hh = col >> 6, hd = col & 63;
                #pragma unroll
                for (int half = 0; half < 2; half++) {
                    int r = row + half * 8;
                    int b = r >> 11, l = r & 2047;
                    size_t off = (((size_t)(b * Hn + hh) * Ln + l) << 6) + hd;
                    float v0 = C[mi][ni][half*2]   * s;
                    float v1 = C[mi][ni][half*2+1] * s;
                    if (z == 0) {
                        uint32_t hw, lw;
                        packhl_h(v0, v1, hw, lw);
                        *(uint32_t*)(g_qh + off) = hw;
                        *(uint32_t*)(g_ql + off) = lw;
                    } else if (z == 1) {
                        *(uint32_t*)(g_k16 + off) = pack2h(v0, v1);
                    } else {
                        *(uint32_t*)(g_v16 + off) = pack2h(v0, v1);
                    }
                }
            }
    } else {
        #pragma unroll
        for (int mi = 0; mi < 2; mi++)
            #pragma unroll
            for (int ni = 0; ni < 4; ni++) {
                int row = row0 + wm * 32 + mi * 16 + (lane >> 2);
                int col = col0 + wn * 32 + ni * 8 + (lane & 3) * 2;
                float2 v0 = make_float2(C[mi][ni][0] * INV_OUT,
                                        C[mi][ni][1] * INV_OUT);
                float2 v1 = make_float2(C[mi][ni][2] * INV_OUT,
                                        C[mi][ni][3] * INV_OUT);
                *(float2*)(outp + (size_t)row * Dn + col) = v0;
                *(float2*)(outp + (size_t)(row + 8) * Dn + col) = v1;
            }
    }
}

// ---------------------------------------------------------------------------
// fp16 2-pass flash attention. Q frags (hi/lo, exact) register-resident;
// K,V single fp16, double-buffered via cp.async.
// Stage (bytes): K 0 (9216), V 9216; stage size 18432, 2 stages.
// Q staged once above the ring: QH at byte 18432+0? -> byte 18432 is stage 1;
// Q uses bytes [18432, 55296) (QH 18432 B at elem 9216, QL at elem 18432),
// consumed into registers before kt=1's issue overwrites stage 1.
// Total smem = 55296 B.
// ---------------------------------------------------------------------------
constexpr int QS = 72;                 // elems per row
constexpr int A_STAGE = 18432;         // bytes per KV stage
constexpr int ATTN_SMEM_BYTES = 55296; // 2 stages + 18432 Q overflow

__global__ void __launch_bounds__(256) attn_kernel()
{
    extern __shared__ uint16_t smh[];
    const uint32_t sb = s2u(smh);

    const int qt   = blockIdx.x;
    const int h    = blockIdx.y;
    const int b    = blockIdx.z;
    const int tid  = threadIdx.x;
    const int lane = tid & 31;
    const int wid  = tid >> 5;
    const int r0   = wid * 16;

    const size_t base = ((size_t)(b * Hn + h) * Ln) * HDn;
    const uint16_t* qh_g = g_qh + base;
    const uint16_t* ql_g = g_ql + base;
    const uint16_t* k_g  = g_k16 + base;
    const uint16_t* v_g  = g_v16 + base;

    // Stage Q tile [128][64] hi/lo at elem offsets 9216 (QH) / 18432 (QL)
    #pragma unroll
    for (int i = 0; i < 4; i++) {
        int idx = tid + i * 256;
        int r = idx >> 3, c8 = idx & 7;
        size_t go = (size_t)(qt * 128 + r) * HDn + c8 * 8;
        *(uint4*)(smh + 9216 + r * QS + c8 * 8)  = *(const uint4*)(qh_g + go);
        *(uint4*)(smh + 18432 + r * QS + c8 * 8) = *(const uint4*)(ql_g + go);
    }

    const int ktmax = 2 * qt + 2;

    auto issue_kv = [&](int kt_, int s_) {
        uint32_t dstb = sb + (uint32_t)s_ * A_STAGE;
        #pragma unroll
        for (int i = 0; i < 4; i++) {
            int p = i >> 1;                    // 0 = K, 1 = V
            int local = (i & 1) * 256 + tid;
            int r = local >> 3, cc = local & 7;
            uint32_t dst = dstb + p * 9216u + (uint32_t)(r * QS + cc * 8) * 2;
            const uint16_t* gp = p ? v_g : k_g;
            cp16(dst, gp + (size_t)(kt_ * 64 + r) * HDn + cc * 8);
        }
    };
    issue_kv(0, 0);
    CP_COMMIT();
    __syncthreads();

    // Extract Q fragments to registers (reused every kt iteration)
    uint32_t qfh[4][4], qfl[4][4];
    #pragma unroll
    for (int ks = 0; ks < 4; ks++) {
        uint32_t qaddr = sb + (uint32_t)((9216 + (r0 + (lane & 15)) * QS
                          + ks * 16 + ((lane >> 4) * 8)) * 2);
        ldm_x4(qfh[ks], qaddr);
        ldm_x4(qfl[ks], qaddr + 9216u * 2);
    }
    __syncthreads();   // Q consumed; stage-1 region may be overwritten

    float m0 = -1e30f, m1 = -1e30f, l0 = 0.f, l1 = 0.f;
    float O[8][4];
    #pragma unroll
    for (int nt = 0; nt < 8; nt++)
        #pragma unroll
        for (int q = 0; q < 4; q++) O[nt][q] = 0.f;

    const int qbase = qt * 128 + r0;

    for (int kt = 0; kt < ktmax; kt++) {
        CP_WAIT0();
        __syncthreads();
        if (kt + 1 < ktmax) {
            issue_kv(kt + 1, (kt + 1) & 1);
            CP_COMMIT();
        }

        if (kt * 64 > qbase + 15) continue;

        const uint32_t stgb = sb + (uint32_t)(kt & 1) * A_STAGE;

        // ---- S = (Qh + Ql) * K^T  (2 MMAs per frag) ----
        float S[8][4];
        #pragma unroll
        for (int nt = 0; nt < 8; nt++)
            #pragma unroll
            for (int q = 0; q < 4; q++) S[nt][q] = 0.f;

        #pragma unroll
        for (int ks = 0; ks < 4; ks++) {
            #pragma unroll
            for (int ntp = 0; ntp < 4; ntp++) {
                uint32_t kaddr = stgb + (uint32_t)(((ntp * 16 + (lane & 7)
                                  + ((lane >> 4) << 3)) * QS
                                  + ((lane >> 3) & 1) * 8 + ks * 16) * 2);
                uint32_t bh[4];
                ldm_x4(bh, kaddr);
                mma_f16(S[2*ntp],   qfh[ks], bh);
                mma_f16(S[2*ntp],   qfl[ks], bh);
                mma_f16(S[2*ntp+1], qfh[ks], bh + 2);
                mma_f16(S[2*ntp+1], qfl[ks], bh + 2);
            }
        }

        // ---- causal mask (diagonal tiles only) ----
        if (kt * 64 + 63 > qbase) {
            int q0 = qbase + (lane >> 2);
            int q1 = q0 + 8;
            #pragma unroll
            for (int nt = 0; nt < 8; nt++) {
                int k0 = kt * 64 + nt * 8 + (lane & 3) * 2;
                if (k0     > q0) S[nt][0] = -1e30f;
                if (k0 + 1 > q0) S[nt][1] = -1e30f;
                if (k0     > q1) S[nt][2] = -1e30f;
                if (k0 + 1 > q1) S[nt][3] = -1e30f;
            }
        }

        // ---- online softmax ----
        float mx0 = -1e30f, mx1 = -1e30f;
        #pragma unroll
        for (int nt = 0; nt < 8; nt++) {
            mx0 = fmaxf(mx0, fmaxf(S[nt][0], S[nt][1]));
            mx1 = fmaxf(mx1, fmaxf(S[nt][2], S[nt][3]));
        }
        mx0 = fmaxf(mx0, __shfl_xor_sync(0xffffffffu, mx0, 1));
        mx0 = fmaxf(mx0, __shfl_xor_sync(0xffffffffu, mx0, 2));
        mx1 = fmaxf(mx1, __shfl_xor_sync(0xffffffffu, mx1, 1));
        mx1 = fmaxf(mx1, __shfl_xor_sync(0xffffffffu, mx1, 2));
        float nm0 = fmaxf(m0, mx0), nm1 = fmaxf(m1, mx1);
        float c0 = __expf(m0 - nm0), c1 = __expf(m1 - nm1);
        float s0 = 0.f, s1 = 0.f;
        #pragma unroll
        for (int nt = 0; nt < 8; nt++) {
            S[nt][0] = __expf(S[nt][0] - nm0);
            S[nt][1] = __expf(S[nt][1] - nm0);
            S[nt][2] = __expf(S[nt][2] - nm1);
            S[nt][3] = __expf(S[nt][3] - nm1);
            s0 += S[nt][0] + S[nt][1];
            s1 += S[nt][2] + S[nt][3];
        }
        s0 += __shfl_xor_sync(0xffffffffu, s0, 1);
        s0 += __shfl_xor_sync(0xffffffffu, s0, 2);
        s1 += __shfl_xor_sync(0xffffffffu, s1, 1);
        s1 += __shfl_xor_sync(0xffffffffu, s1, 2);
        m0 = nm0; m1 = nm1;
        l0 = l0 * c0 + s0;
        l1 = l1 * c1 + s1;
        #pragma unroll
        for (int nt = 0; nt < 8; nt++) {
            O[nt][0] *= c0; O[nt][1] *= c0;
            O[nt][2] *= c1; O[nt][3] *= c1;
        }

        // ---- O += (Ph + Pl) * V  (2 MMAs per frag) ----
        #pragma unroll
        for (int g = 0; g < 4; g++) {
            uint32_t ah[4], al[4];
            packhl_h(S[2*g][0],   S[2*g][1],   ah[0], al[0]);
            packhl_h(S[2*g][2],   S[2*g][3],   ah[1], al[1]);
            packhl_h(S[2*g+1][0], S[2*g+1][1], ah[2], al[2]);
            packhl_h(S[2*g+1][2], S[2*g+1][3], ah[3], al[3]);
            #pragma unroll
            for (int ntp = 0; ntp < 4; ntp++) {
                uint32_t vaddr = stgb + 9216u
                    + (uint32_t)(((g * 16 + (lane & 15)) * QS
                                  + ntp * 16 + ((lane >> 4) << 3)) * 2);
                uint32_t vh[4];
                ldm_x4t(vh, vaddr);
                mma_f16(O[2*ntp],   ah, vh);
                mma_f16(O[2*ntp],   al, vh);
                mma_f16(O[2*ntp+1], ah, vh + 2);
                mma_f16(O[2*ntp+1], al, vh + 2);
            }
        }
    }

    // Finalize: scale by SC_Y/l, store y as fp16 hi/lo for out-proj
    float il0 = SC_Y / l0, il1 = SC_Y / l1;
    int rowg = qt * 128 + r0 + (lane >> 2);
    #pragma unroll
    for (int nt = 0; nt < 8; nt++) {
        int hd = nt * 8 + (lane & 3) * 2;
        size_t o0 = (size_t)(b * Ln + rowg) * Dn + h * 64 + hd;
        size_t o1 = (size_t)(b * Ln + rowg + 8) * Dn + h * 64 + hd;
        uint32_t hw, lw;
        packhl_h(O[nt][0] * il0, O[nt][1] * il0, hw, lw);
        *(uint32_t*)(g_yh + o0) = hw;
        *(uint32_t*)(g_yl + o0) = lw;
        packhl_h(O[nt][2] * il1, O[nt][3] * il1, hw, lw);
        *(uint32_t*)(g_yh + o1) = hw;
        *(uint32_t*)(g_yl + o1) = lw;
    }
}

// ---------------------------------------------------------------------------
extern "C" void kernel_launch(void* const* d_in, const int* in_sizes, int n_in,
                              void* d_out, int out_size)
{
    (void)in_sizes; (void)n_in; (void)out_size;
    const float* x  = (const float*)d_in[0];
    const float* Wq = (const float*)d_in[1];
    const float* Wk = (const float*)d_in[2];
    const float* Wv = (const float*)d_in[3];
    const float* Wo = (const float*)d_in[4];
    float* out = (float*)d_out;

    cudaFuncSetAttribute(gemm_mma_kernel,
                         cudaFuncAttributeMaxDynamicSharedMemorySize,
                         GEMM_SMEM_BYTES);
    cudaFuncSetAttribute(attn_kernel,
                         cudaFuncAttributeMaxDynamicSharedMemorySize,
                         ATTN_SMEM_BYTES);

    prep_kernel<<<8192, 256>>>(x, Wq, Wk, Wv, Wo);
    gemm_mma_kernel<<<dim3(Dn/64, NROW/128, 3), 256, GEMM_SMEM_BYTES>>>(nullptr, 0);
    attn_kernel<<<dim3(Ln/128, Hn, Bn), 256, ATTN_SMEM_BYTES>>>();
    gemm_mma_kernel<<<dim3(Dn/64, NROW/128, 1), 256, GEMM_SMEM_BYTES>>>(out, 1);
}

// round 11
// speedup vs baseline: 3.5341x; 1.0954x over previous
#include <cuda_runtime.h>
#include <cuda_bf16.h>
#include <cuda_fp16.h>
#include <cstdint>

// Problem constants
constexpr int Bn  = 2;
constexpr int Ln  = 2048;
constexpr int Dn  = 1024;
constexpr int Hn  = 16;
constexpr int HDn = 64;
constexpr int NROW = Bn * Ln;   // 4096
constexpr size_t PLANE = (size_t)Bn * Hn * Ln * HDn;  // 4M elems

// Scaling
constexpr float SC_X = 16.f;    // x stored as fp16(16x) single
constexpr float SC_W = 32.f;    // weights stored as fp16(32W)
constexpr float SC_Y = 256.f;   // attn output stored as fp16(256y) hi/lo
constexpr float INV_QKV = 1.f / (16.f * 32.f);    // 1/512
constexpr float INV_OUT = 1.f / (256.f * 32.f);   // 1/8192

// Scratch (device globals: allocation-free)
__device__ uint16_t g_x16[(size_t)NROW * Dn];     // fp16 of 16*x, [m][k]
__device__ uint16_t g_w16[(size_t)4 * Dn * Dn];   // fp16(32W): Wq,Wk,Wv,Wo [k][n]
__device__ uint16_t g_qh[PLANE];                  // fp16 hi of 0.5*q, [B,H,L,HD]
__device__ uint16_t g_ql[PLANE];                  // fp16 lo
__device__ uint16_t g_k16[PLANE];                 // fp16 of 0.25*k
__device__ uint16_t g_v16[PLANE];                 // fp16 of v
__device__ uint16_t g_yh[(size_t)NROW * Dn];      // fp16 hi of 256*y
__device__ uint16_t g_yl[(size_t)NROW * Dn];      // fp16 lo

// ---------------------------------------------------------------------------
// Helpers
// ---------------------------------------------------------------------------
__device__ __forceinline__ uint32_t s2u(const void* p) {
    uint32_t a;
    asm("{ .reg .u64 t; cvta.to.shared.u64 t, %1; cvt.u32.u64 %0, t; }"
        : "=r"(a) : "l"(p));
    return a;
}
__device__ __forceinline__ void cp16(uint32_t dst, const void* src) {
    asm volatile("cp.async.cg.shared.global [%0], [%1], 16;"
                 :: "r"(dst), "l"(src) : "memory");
}
#define CP_COMMIT() asm volatile("cp.async.commit_group;" ::: "memory")
#define CP_WAIT0()  asm volatile("cp.async.wait_group 0;" ::: "memory")

__device__ __forceinline__ void ldm_x4(uint32_t* r, uint32_t a) {
    asm volatile("ldmatrix.sync.aligned.m8n8.x4.shared.b16 {%0,%1,%2,%3}, [%4];"
                 : "=r"(r[0]), "=r"(r[1]), "=r"(r[2]), "=r"(r[3]) : "r"(a));
}
__device__ __forceinline__ void ldm_x4t(uint32_t* r, uint32_t a) {
    asm volatile("ldmatrix.sync.aligned.m8n8.x4.trans.shared.b16 {%0,%1,%2,%3}, [%4];"
                 : "=r"(r[0]), "=r"(r[1]), "=r"(r[2]), "=r"(r[3]) : "r"(a));
}
__device__ __forceinline__ void mma_f16(float* c, const uint32_t* a,
                                        const uint32_t* b) {
    asm volatile(
        "mma.sync.aligned.m16n8k16.row.col.f32.f16.f16.f32 "
        "{%0,%1,%2,%3}, {%4,%5,%6,%7}, {%8,%9}, {%0,%1,%2,%3};"
        : "+f"(c[0]), "+f"(c[1]), "+f"(c[2]), "+f"(c[3])
        : "r"(a[0]), "r"(a[1]), "r"(a[2]), "r"(a[3]), "r"(b[0]), "r"(b[1]));
}
// fp16 helpers
__device__ __forceinline__ uint16_t hfu(float f) {
    __half h = __float2half_rn(f);
    return *(uint16_t*)&h;
}
__device__ __forceinline__ float hff(uint16_t u) {
    __half h = *(__half*)&u;
    return __half2float(h);
}
__device__ __forceinline__ uint2 pack4h(float4 v) {
    uint16_t h0 = hfu(v.x), h1 = hfu(v.y), h2 = hfu(v.z), h3 = hfu(v.w);
    return make_uint2((uint32_t)h0 | ((uint32_t)h1 << 16),
                      (uint32_t)h2 | ((uint32_t)h3 << 16));
}
__device__ __forceinline__ void packhl_h(float f0, float f1,
                                         uint32_t& h2, uint32_t& l2) {
    uint16_t h0 = hfu(f0), h1 = hfu(f1);
    uint16_t l0 = hfu(f0 - hff(h0)), l1 = hfu(f1 - hff(h1));
    h2 = (uint32_t)h0 | ((uint32_t)h1 << 16);
    l2 = (uint32_t)l0 | ((uint32_t)l1 << 16);
}
__device__ __forceinline__ uint32_t pack2h(float f0, float f1) {
    return (uint32_t)hfu(f0) | ((uint32_t)hfu(f1) << 16);
}

// ---------------------------------------------------------------------------
// Prep: x -> fp16(16x) single [m][k]; all 4 weights -> fp16(32W) [k][n].
// ---------------------------------------------------------------------------
__global__ void __launch_bounds__(256) prep_kernel(
    const float* __restrict__ x,
    const float* __restrict__ Wq, const float* __restrict__ Wk,
    const float* __restrict__ Wv, const float* __restrict__ Wo)
{
    int i = blockIdx.x * 256 + threadIdx.x;   // float4 index
    if (i < (1 << 20)) {
        float4 v = ((const float4*)x)[i];
        v.x *= SC_X; v.y *= SC_X; v.z *= SC_X; v.w *= SC_X;
        ((uint2*)g_x16)[i] = pack4h(v);
    } else {
        int j = i - (1 << 20);
        int slot = j >> 18;                    // 0..3 = Wq,Wk,Wv,Wo
        int off  = j & ((1 << 18) - 1);
        const float* w = (slot == 0) ? Wq : (slot == 1) ? Wk
                        : (slot == 2) ? Wv : Wo;
        float4 v = ((const float4*)w)[off];
        v.x *= SC_W; v.y *= SC_W; v.z *= SC_W; v.w *= SC_W;
        ((uint2*)g_w16)[((size_t)slot << 18) + off] = pack4h(v);
    }
}

// ---------------------------------------------------------------------------
// fp16 GEMM: 128x64 CTA tile, 8 warps (4m x 2n), warp tile 32x32.
// mode 0 (QKV): A = x single fp16 (1-pass, 8 MMAs/chunk).
// mode 1 (out): A = y hi/lo fp16 (2-pass, exact A, 16 MMAs/chunk).
// 2-stage cp.async. Stage: Ah 0 (10240 B), Al 10240 (mode1 only), B 20480.
// ---------------------------------------------------------------------------
constexpr int G_STAGE = 25088;
constexpr int GEMM_SMEM_BYTES = 2 * G_STAGE;   // 50176

__global__ void __launch_bounds__(256, 2) gemm_mma_kernel(
    float* __restrict__ outp, int mode)
{
    extern __shared__ uint16_t smg[];
    const uint32_t sb = s2u(smg);

    const int tid  = threadIdx.x;
    const int lane = tid & 31;
    const int w    = tid >> 5;
    const int wm   = w & 3;
    const int wn   = w >> 2;
    const int col0 = blockIdx.x * 64;
    const int row0 = blockIdx.y * 128;
    const int z    = blockIdx.z;

    const uint16_t* Aph = (mode == 0) ? g_x16 : g_yh;
    const uint16_t* Apl = g_yl;                  // used only in mode 1
    const int slot = (mode == 0) ? z : 3;
    const uint16_t* Bp = g_w16 + ((size_t)slot << 20);

    float C[2][4][4];
    #pragma unroll
    for (int mi = 0; mi < 2; mi++)
        #pragma unroll
        for (int ni = 0; ni < 4; ni++)
            #pragma unroll
            for (int q = 0; q < 4; q++) C[mi][ni][q] = 0.f;

    auto issue = [&](int c_, int s_) {
        uint32_t dstb = sb + (uint32_t)s_ * G_STAGE;
        int k0 = c_ * 32;
        // A hi plane (always)
        #pragma unroll
        for (int i = 0; i < 2; i++) {
            int local = i * 256 + tid;
            int r = local >> 2, cc = local & 3;
            uint32_t dst = dstb + (uint32_t)(r * 40 + cc * 8) * 2;
            cp16(dst, Aph + (size_t)(row0 + r) * Dn + k0 + cc * 8);
        }
        // A lo plane (mode 1 only)
        if (mode == 1) {
            #pragma unroll
            for (int i = 0; i < 2; i++) {
                int local = i * 256 + tid;
                int r = local >> 2, cc = local & 3;
                uint32_t dst = dstb + 10240u + (uint32_t)(r * 40 + cc * 8) * 2;
                cp16(dst, Apl + (size_t)(row0 + r) * Dn + k0 + cc * 8);
            }
        }
        // B single
        {
            int kk = tid >> 3, cc = tid & 7;
            uint32_t dst = dstb + 20480u + (uint32_t)(kk * 72 + cc * 8) * 2;
            cp16(dst, Bp + (size_t)(k0 + kk) * Dn + col0 + cc * 8);
        }
    };

    issue(0, 0);
    CP_COMMIT();

    for (int c = 0; c < 32; c++) {
        CP_WAIT0();
        __syncthreads();
        if (c + 1 < 32) {
            issue(c + 1, (c + 1) & 1);
            CP_COMMIT();
        }
        const uint32_t stgb = sb + (uint32_t)(c & 1) * G_STAGE;

        #pragma unroll
        for (int ks = 0; ks < 2; ks++) {
            uint32_t ahf[2][4], alf[2][4], bf[4][2];
            #pragma unroll
            for (int mi = 0; mi < 2; mi++) {
                uint32_t off = (uint32_t)((wm * 32 + mi * 16 + (lane & 15)) * 80
                                          + ks * 32 + ((lane >> 4) * 16));
                ldm_x4(ahf[mi], stgb + off);
                if (mode == 1) ldm_x4(alf[mi], stgb + 10240u + off);
            }
            #pragma unroll
            for (int g = 0; g < 2; g++) {
                uint32_t off = 20480u
                    + (uint32_t)((ks * 16 + (lane & 15)) * 144
                                 + (wn * 32 + g * 16 + ((lane >> 4) * 8)) * 2);
                uint32_t t[4];
                ldm_x4t(t, stgb + off);
                bf[g*2][0]   = t[0]; bf[g*2][1]   = t[1];
                bf[g*2+1][0] = t[2]; bf[g*2+1][1] = t[3];
            }
            #pragma unroll
            for (int mi = 0; mi < 2; mi++)
                #pragma unroll
                for (int ni = 0; ni < 4; ni++) {
                    mma_f16(C[mi][ni], ahf[mi], bf[ni]);
                    if (mode == 1) mma_f16(C[mi][ni], alf[mi], bf[ni]);
                }
        }
    }

    if (mode == 0) {
        // z=0: Q stored as fp16 hi/lo of 0.5*q (0.5*0.25 = softmax 0.125 w/ K)
        // z=1: K stored single fp16 of 0.25*k ;  z=2: V stored single fp16
        const float s = INV_QKV * ((z == 0) ? 0.5f : (z == 1) ? 0.25f : 1.f);
        #pragma unroll
        for (int mi = 0; mi < 2; mi++)
            #pragma unroll
            for (int ni = 0; ni < 4; ni++) {
                int row = row0 + wm * 32 + mi * 16 + (lane >> 2);
                int col = col0 + wn * 32 + ni * 8 + (lane & 3) * 2;
                int hh = col >> 6, hd = col & 63;
                #pragma unroll
                for (int half = 0; half < 2; half++) {
                    int r = row + half * 8;
                    int b = r >> 11, l = r & 2047;
                    size_t off = (((size_t)(b * Hn + hh) * Ln + l) << 6) + hd;
                    float v0 = C[mi][ni][half*2]   * s;
                    float v1 = C[mi][ni][half*2+1] * s;
                    if (z == 0) {
                        uint32_t hw, lw;
                        packhl_h(v0, v1, hw, lw);
                        *(uint32_t*)(g_qh + off) = hw;
                        *(uint32_t*)(g_ql + off) = lw;
                    } else if (z == 1) {
                        *(uint32_t*)(g_k16 + off) = pack2h(v0, v1);
                    } else {
                        *(uint32_t*)(g_v16 + off) = pack2h(v0, v1);
                    }
                }
            }
    } else {
        #pragma unroll
        for (int mi = 0; mi < 2; mi++)
            #pragma unroll
            for (int ni = 0; ni < 4; ni++) {
                int row = row0 + wm * 32 + mi * 16 + (lane >> 2);
                int col = col0 + wn * 32 + ni * 8 + (lane & 3) * 2;
                float2 v0 = make_float2(C[mi][ni][0] * INV_OUT,
                                        C[mi][ni][1] * INV_OUT);
                float2 v1 = make_float2(C[mi][ni][2] * INV_OUT,
                                        C[mi][ni][3] * INV_OUT);
                *(float2*)(outp + (size_t)row * Dn + col) = v0;
                *(float2*)(outp + (size_t)(row + 8) * Dn + col) = v1;
            }
    }
}

// ---------------------------------------------------------------------------
// fp16 2-pass flash attention (unchanged from round 10).
// Q frags (hi/lo, exact) register-resident; K,V single fp16, double-buffered.
// Stage (bytes): K 0 (9216), V 9216; stage size 18432, 2 stages.
// Q staged once above the ring (bytes [18432, 55296)), consumed pre-loop.
// ---------------------------------------------------------------------------
constexpr int QS = 72;                 // elems per row
constexpr int A_STAGE = 18432;         // bytes per KV stage
constexpr int ATTN_SMEM_BYTES = 55296;

__global__ void __launch_bounds__(256) attn_kernel()
{
    extern __shared__ uint16_t smh[];
    const uint32_t sb = s2u(smh);

    const int qt   = blockIdx.x;
    const int h    = blockIdx.y;
    const int b    = blockIdx.z;
    const int tid  = threadIdx.x;
    const int lane = tid & 31;
    const int wid  = tid >> 5;
    const int r0   = wid * 16;

    const size_t base = ((size_t)(b * Hn + h) * Ln) * HDn;
    const uint16_t* qh_g = g_qh + base;
    const uint16_t* ql_g = g_ql + base;
    const uint16_t* k_g  = g_k16 + base;
    const uint16_t* v_g  = g_v16 + base;

    // Stage Q tile [128][64] hi/lo at elem offsets 9216 (QH) / 18432 (QL)
    #pragma unroll
    for (int i = 0; i < 4; i++) {
        int idx = tid + i * 256;
        int r = idx >> 3, c8 = idx & 7;
        size_t go = (size_t)(qt * 128 + r) * HDn + c8 * 8;
        *(uint4*)(smh + 9216 + r * QS + c8 * 8)  = *(const uint4*)(qh_g + go);
        *(uint4*)(smh + 18432 + r * QS + c8 * 8) = *(const uint4*)(ql_g + go);
    }

    const int ktmax = 2 * qt + 2;

    auto issue_kv = [&](int kt_, int s_) {
        uint32_t dstb = sb + (uint32_t)s_ * A_STAGE;
        #pragma unroll
        for (int i = 0; i < 4; i++) {
            int p = i >> 1;                    // 0 = K, 1 = V
            int local = (i & 1) * 256 + tid;
            int r = local >> 3, cc = local & 7;
            uint32_t dst = dstb + p * 9216u + (uint32_t)(r * QS + cc * 8) * 2;
            const uint16_t* gp = p ? v_g : k_g;
            cp16(dst, gp + (size_t)(kt_ * 64 + r) * HDn + cc * 8);
        }
    };
    issue_kv(0, 0);
    CP_COMMIT();
    __syncthreads();

    // Extract Q fragments to registers (reused every kt iteration)
    uint32_t qfh[4][4], qfl[4][4];
    #pragma unroll
    for (int ks = 0; ks < 4; ks++) {
        uint32_t qaddr = sb + (uint32_t)((9216 + (r0 + (lane & 15)) * QS
                          + ks * 16 + ((lane >> 4) * 8)) * 2);
        ldm_x4(qfh[ks], qaddr);
        ldm_x4(qfl[ks], qaddr + 9216u * 2);
    }
    __syncthreads();   // Q consumed; stage-1 region may be overwritten

    float m0 = -1e30f, m1 = -1e30f, l0 = 0.f, l1 = 0.f;
    float O[8][4];
    #pragma unroll
    for (int nt = 0; nt < 8; nt++)
        #pragma unroll
        for (int q = 0; q < 4; q++) O[nt][q] = 0.f;

    const int qbase = qt * 128 + r0;

    for (int kt = 0; kt < ktmax; kt++) {
        CP_WAIT0();
        __syncthreads();
        if (kt + 1 < ktmax) {
            issue_kv(kt + 1, (kt + 1) & 1);
            CP_COMMIT();
        }

        if (kt * 64 > qbase + 15) continue;

        const uint32_t stgb = sb + (uint32_t)(kt & 1) * A_STAGE;

        // ---- S = (Qh + Ql) * K^T ----
        float S[8][4];
        #pragma unroll
        for (int nt = 0; nt < 8; nt++)
            #pragma unroll
            for (int q = 0; q < 4; q++) S[nt][q] = 0.f;

        #pragma unroll
        for (int ks = 0; ks < 4; ks++) {
            #pragma unroll
            for (int ntp = 0; ntp < 4; ntp++) {
                uint32_t kaddr = stgb + (uint32_t)(((ntp * 16 + (lane & 7)
                                  + ((lane >> 4) << 3)) * QS
                                  + ((lane >> 3) & 1) * 8 + ks * 16) * 2);
                uint32_t bh[4];
                ldm_x4(bh, kaddr);
                mma_f16(S[2*ntp],   qfh[ks], bh);
                mma_f16(S[2*ntp],   qfl[ks], bh);
                mma_f16(S[2*ntp+1], qfh[ks], bh + 2);
                mma_f16(S[2*ntp+1], qfl[ks], bh + 2);
            }
        }

        // ---- causal mask (diagonal tiles only) ----
        if (kt * 64 + 63 > qbase) {
            int q0 = qbase + (lane >> 2);
            int q1 = q0 + 8;
            #pragma unroll
            for (int nt = 0; nt < 8; nt++) {
                int k0 = kt * 64 + nt * 8 + (lane & 3) * 2;
                if (k0     > q0) S[nt][0] = -1e30f;
                if (k0 + 1 > q0) S[nt][1] = -1e30f;
                if (k0     > q1) S[nt][2] = -1e30f;
                if (k0 + 1 > q1) S[nt][3] = -1e30f;
            }
        }

        // ---- online softmax ----
        float mx0 = -1e30f, mx1 = -1e30f;
        #pragma unroll
        for (int nt = 0; nt < 8; nt++) {
            mx0 = fmaxf(mx0, fmaxf(S[nt][0], S[nt][1]));
            mx1 = fmaxf(mx1, fmaxf(S[nt][2], S[nt][3]));
        }
        mx0 = fmaxf(mx0, __shfl_xor_sync(0xffffffffu, mx0, 1));
        mx0 = fmaxf(mx0, __shfl_xor_sync(0xffffffffu, mx0, 2));
        mx1 = fmaxf(mx1, __shfl_xor_sync(0xffffffffu, mx1, 1));
        mx1 = fmaxf(mx1, __shfl_xor_sync(0xffffffffu, mx1, 2));
        float nm0 = fmaxf(m0, mx0), nm1 = fmaxf(m1, mx1);
        float c0 = __expf(m0 - nm0), c1 = __expf(m1 - nm1);
        float s0 = 0.f, s1 = 0.f;
        #pragma unroll
        for (int nt = 0; nt < 8; nt++) {
            S[nt][0] = __expf(S[nt][0] - nm0);
            S[nt][1] = __expf(S[nt][1] - nm0);
            S[nt][2] = __expf(S[nt][2] - nm1);
            S[nt][3] = __expf(S[nt][3] - nm1);
            s0 += S[nt][0] + S[nt][1];
            s1 += S[nt][2] + S[nt][3];
        }
        s0 += __shfl_xor_sync(0xffffffffu, s0, 1);
        s0 += __shfl_xor_sync(0xffffffffu, s0, 2);
        s1 += __shfl_xor_sync(0xffffffffu, s1, 1);
        s1 += __shfl_xor_sync(0xffffffffu, s1, 2);
        m0 = nm0; m1 = nm1;
        l0 = l0 * c0 + s0;
        l1 = l1 * c1 + s1;
        #pragma unroll
        for (int nt = 0; nt < 8; nt++) {
            O[nt][0] *= c0; O[nt][1] *= c0;
            O[nt][2] *= c1; O[nt][3] *= c1;
        }

        // ---- O += (Ph + Pl) * V ----
        #pragma unroll
        for (int g = 0; g < 4; g++) {
            uint32_t ah[4], al[4];
            packhl_h(S[2*g][0],   S[2*g][1],   ah[0], al[0]);
            packhl_h(S[2*g][2],   S[2*g][3],   ah[1], al[1]);
            packhl_h(S[2*g+1][0], S[2*g+1][1], ah[2], al[2]);
            packhl_h(S[2*g+1][2], S[2*g+1][3], ah[3], al[3]);
            #pragma unroll
            for (int ntp = 0; ntp < 4; ntp++) {
                uint32_t vaddr = stgb + 9216u
                    + (uint32_t)(((g * 16 + (lane & 15)) * QS
                                  + ntp * 16 + ((lane >> 4) << 3)) * 2);
                uint32_t vh[4];
                ldm_x4t(vh, vaddr);
                mma_f16(O[2*ntp],   ah, vh);
                mma_f16(O[2*ntp],   al, vh);
                mma_f16(O[2*ntp+1], ah, vh + 2);
                mma_f16(O[2*ntp+1], al, vh + 2);
            }
        }
    }

    // Finalize: scale by SC_Y/l, store y as fp16 hi/lo for out-proj
    float il0 = SC_Y / l0, il1 = SC_Y / l1;
    int rowg = qt * 128 + r0 + (lane >> 2);
    #pragma unroll
    for (int nt = 0; nt < 8; nt++) {
        int hd = nt * 8 + (lane & 3) * 2;
        size_t o0 = (size_t)(b * Ln + rowg) * Dn + h * 64 + hd;
        size_t o1 = (size_t)(b * Ln + rowg + 8) * Dn + h * 64 + hd;
        uint32_t hw, lw;
        packhl_h(O[nt][0] * il0, O[nt][1] * il0, hw, lw);
        *(uint32_t*)(g_yh + o0) = hw;
        *(uint32_t*)(g_yl + o0) = lw;
        packhl_h(O[nt][2] * il1, O[nt][3] * il1, hw, lw);
        *(uint32_t*)(g_yh + o1) = hw;
        *(uint32_t*)(g_yl + o1) = lw;
    }
}

// ---------------------------------------------------------------------------
extern "C" void kernel_launch(void* const* d_in, const int* in_sizes, int n_in,
                              void* d_out, int out_size)
{
    (void)in_sizes; (void)n_in; (void)out_size;
    const float* x  = (const float*)d_in[0];
    const float* Wq = (const float*)d_in[1];
    const float* Wk = (const float*)d_in[2];
    const float* Wv = (const float*)d_in[3];
    const float* Wo = (const float*)d_in[4];
    float* out = (float*)d_out;

    cudaFuncSetAttribute(gemm_mma_kernel,
                         cudaFuncAttributeMaxDynamicSharedMemorySize,
                         GEMM_SMEM_BYTES);
    cudaFuncSetAttribute(attn_kernel,
                         cudaFuncAttributeMaxDynamicSharedMemorySize,
                         ATTN_SMEM_BYTES);

    prep_kernel<<<8192, 256>>>(x, Wq, Wk, Wv, Wo);
    gemm_mma_kernel<<<dim3(Dn/64, NROW/128, 3), 256, GEMM_SMEM_BYTES>>>(nullptr, 0);
    attn_kernel<<<dim3(Ln/128, Hn, Bn), 256, ATTN_SMEM_BYTES>>>();
    gemm_mma_kernel<<<dim3(Dn/64, NROW/128, 1), 256, GEMM_SMEM_BYTES>>>(out, 1);
}

// round 12
// speedup vs baseline: 4.1395x; 1.1713x over previous
#include <cuda_runtime.h>
#include <cuda_bf16.h>
#include <cuda_fp16.h>
#include <cstdint>

// Problem constants
constexpr int Bn  = 2;
constexpr int Ln  = 2048;
constexpr int Dn  = 1024;
constexpr int Hn  = 16;
constexpr int HDn = 64;
constexpr int NROW = Bn * Ln;   // 4096
constexpr size_t PLANE = (size_t)Bn * Hn * Ln * HDn;  // 4M elems

// Scaling
constexpr float SC_X = 16.f;
constexpr float SC_W = 32.f;
constexpr float SC_Y = 256.f;
constexpr float INV_QKV = 1.f / (16.f * 32.f);    // 1/512
constexpr float INV_OUT = 1.f / (256.f * 32.f);   // 1/8192

// Scratch (device globals: allocation-free)
__device__ uint16_t g_x16[(size_t)NROW * Dn];     // fp16 of 16*x, [m][k]
__device__ uint16_t g_w16[(size_t)4 * Dn * Dn];   // fp16(32W): Wq,Wk,Wv,Wo [k][n]
__device__ uint16_t g_qh[PLANE];                  // fp16 hi of 0.5*q
__device__ uint16_t g_ql[PLANE];                  // fp16 lo
__device__ uint16_t g_k16[PLANE];                 // fp16 of 0.25*k
__device__ uint16_t g_v16[PLANE];                 // fp16 of v
__device__ uint16_t g_yh[(size_t)NROW * Dn];      // fp16 hi of 256*y
__device__ uint16_t g_yl[(size_t)NROW * Dn];      // fp16 lo

// ---------------------------------------------------------------------------
// Helpers
// ---------------------------------------------------------------------------
__device__ __forceinline__ uint32_t s2u(const void* p) {
    uint32_t a;
    asm("{ .reg .u64 t; cvta.to.shared.u64 t, %1; cvt.u32.u64 %0, t; }"
        : "=r"(a) : "l"(p));
    return a;
}
__device__ __forceinline__ void cp16(uint32_t dst, const void* src) {
    asm volatile("cp.async.cg.shared.global [%0], [%1], 16;"
                 :: "r"(dst), "l"(src) : "memory");
}
#define CP_COMMIT() asm volatile("cp.async.commit_group;" ::: "memory")
#define CP_WAIT0()  asm volatile("cp.async.wait_group 0;" ::: "memory")

__device__ __forceinline__ void ldm_x4(uint32_t* r, uint32_t a) {
    asm volatile("ldmatrix.sync.aligned.m8n8.x4.shared.b16 {%0,%1,%2,%3}, [%4];"
                 : "=r"(r[0]), "=r"(r[1]), "=r"(r[2]), "=r"(r[3]) : "r"(a));
}
__device__ __forceinline__ void ldm_x4t(uint32_t* r, uint32_t a) {
    asm volatile("ldmatrix.sync.aligned.m8n8.x4.trans.shared.b16 {%0,%1,%2,%3}, [%4];"
                 : "=r"(r[0]), "=r"(r[1]), "=r"(r[2]), "=r"(r[3]) : "r"(a));
}
__device__ __forceinline__ void mma_f16(float* c, const uint32_t* a,
                                        const uint32_t* b) {
    asm volatile(
        "mma.sync.aligned.m16n8k16.row.col.f32.f16.f16.f32 "
        "{%0,%1,%2,%3}, {%4,%5,%6,%7}, {%8,%9}, {%0,%1,%2,%3};"
        : "+f"(c[0]), "+f"(c[1]), "+f"(c[2]), "+f"(c[3])
        : "r"(a[0]), "r"(a[1]), "r"(a[2]), "r"(a[3]), "r"(b[0]), "r"(b[1]));
}
// fp16 helpers
__device__ __forceinline__ uint16_t hfu(float f) {
    __half h = __float2half_rn(f);
    return *(uint16_t*)&h;
}
__device__ __forceinline__ float hff(uint16_t u) {
    __half h = *(__half*)&u;
    return __half2float(h);
}
__device__ __forceinline__ uint2 pack4h(float4 v) {
    uint16_t h0 = hfu(v.x), h1 = hfu(v.y), h2 = hfu(v.z), h3 = hfu(v.w);
    return make_uint2((uint32_t)h0 | ((uint32_t)h1 << 16),
                      (uint32_t)h2 | ((uint32_t)h3 << 16));
}
__device__ __forceinline__ void packhl_h(float f0, float f1,
                                         uint32_t& h2, uint32_t& l2) {
    uint16_t h0 = hfu(f0), h1 = hfu(f1);
    uint16_t l0 = hfu(f0 - hff(h0)), l1 = hfu(f1 - hff(h1));
    h2 = (uint32_t)h0 | ((uint32_t)h1 << 16);
    l2 = (uint32_t)l0 | ((uint32_t)l1 << 16);
}
__device__ __forceinline__ uint32_t pack2h(float f0, float f1) {
    return (uint32_t)hfu(f0) | ((uint32_t)hfu(f1) << 16);
}

// ---------------------------------------------------------------------------
// Prep: x -> fp16(16x) single [m][k]; all 4 weights -> fp16(32W) [k][n].
// ---------------------------------------------------------------------------
__global__ void __launch_bounds__(256) prep_kernel(
    const float* __restrict__ x,
    const float* __restrict__ Wq, const float* __restrict__ Wk,
    const float* __restrict__ Wv, const float* __restrict__ Wo)
{
    int i = blockIdx.x * 256 + threadIdx.x;   // float4 index
    if (i < (1 << 20)) {
        float4 v = ((const float4*)x)[i];
        v.x *= SC_X; v.y *= SC_X; v.z *= SC_X; v.w *= SC_X;
        ((uint2*)g_x16)[i] = pack4h(v);
    } else {
        int j = i - (1 << 20);
        int slot = j >> 18;
        int off  = j & ((1 << 18) - 1);
        const float* w = (slot == 0) ? Wq : (slot == 1) ? Wk
                        : (slot == 2) ? Wv : Wo;
        float4 v = ((const float4*)w)[off];
        v.x *= SC_W; v.y *= SC_W; v.z *= SC_W; v.w *= SC_W;
        ((uint2*)g_w16)[((size_t)slot << 18) + off] = pack4h(v);
    }
}

// ---------------------------------------------------------------------------
// fp16 GEMM, BK=64: 128x64 CTA tile, 8 warps (4m x 2n), warp tile 32x32.
// mode 0 (QKV): A = x single fp16 (1-pass). mode 1 (out): A = y hi/lo (2-pass).
// 2-stage cp.async, 16 chunks. Stage layout (bytes):
//   Ah [0, 18432)  (128 rows x 144 B stride)
//   B  [18432, 27648)  (64 rows x 144 B)
//   Al [27648, 46080)  (mode 1 only)
// stage stride: mode0 = 27648, mode1 = 46080 (runtime).
// ---------------------------------------------------------------------------
constexpr int G_STAGE0 = 27648;
constexpr int G_STAGE1 = 46080;
constexpr int GEMM_SMEM0 = 2 * G_STAGE0;   // 55296
constexpr int GEMM_SMEM1 = 2 * G_STAGE1;   // 92160

__global__ void __launch_bounds__(256, 2) gemm_mma_kernel(
    float* __restrict__ outp, int mode)
{
    extern __shared__ uint16_t smg[];
    const uint32_t sb = s2u(smg);
    const uint32_t sstride = (mode == 0) ? G_STAGE0 : G_STAGE1;

    const int tid  = threadIdx.x;
    const int lane = tid & 31;
    const int w    = tid >> 5;
    const int wm   = w & 3;
    const int wn   = w >> 2;
    const int col0 = blockIdx.x * 64;
    const int row0 = blockIdx.y * 128;
    const int z    = blockIdx.z;

    const uint16_t* Aph = (mode == 0) ? g_x16 : g_yh;
    const uint16_t* Apl = g_yl;
    const int slot = (mode == 0) ? z : 3;
    const uint16_t* Bp = g_w16 + ((size_t)slot << 20);

    float C[2][4][4];
    #pragma unroll
    for (int mi = 0; mi < 2; mi++)
        #pragma unroll
        for (int ni = 0; ni < 4; ni++)
            #pragma unroll
            for (int q = 0; q < 4; q++) C[mi][ni][q] = 0.f;

    auto issue = [&](int c_, int s_) {
        uint32_t dstb = sb + (uint32_t)s_ * sstride;
        int k0 = c_ * 64;
        // A hi: 128 rows x 64 elems = 1024 cp16 (4/thread)
        #pragma unroll
        for (int i = 0; i < 4; i++) {
            int local = i * 256 + tid;
            int r = local >> 3, cc = local & 7;
            uint32_t dst = dstb + (uint32_t)(r * 144 + cc * 16);
            cp16(dst, Aph + (size_t)(row0 + r) * Dn + k0 + cc * 8);
        }
        // B: 64 rows x 64 elems = 512 cp16 (2/thread)
        #pragma unroll
        for (int i = 0; i < 2; i++) {
            int local = i * 256 + tid;
            int kk = local >> 3, cc = local & 7;
            uint32_t dst = dstb + 18432u + (uint32_t)(kk * 144 + cc * 16);
            cp16(dst, Bp + (size_t)(k0 + kk) * Dn + col0 + cc * 8);
        }
        // A lo (mode 1 only)
        if (mode == 1) {
            #pragma unroll
            for (int i = 0; i < 4; i++) {
                int local = i * 256 + tid;
                int r = local >> 3, cc = local & 7;
                uint32_t dst = dstb + 27648u + (uint32_t)(r * 144 + cc * 16);
                cp16(dst, Apl + (size_t)(row0 + r) * Dn + k0 + cc * 8);
            }
        }
    };

    issue(0, 0);
    CP_COMMIT();

    for (int c = 0; c < 16; c++) {
        CP_WAIT0();
        __syncthreads();
        if (c + 1 < 16) {
            issue(c + 1, (c + 1) & 1);
            CP_COMMIT();
        }
        const uint32_t stgb = sb + (uint32_t)(c & 1) * sstride;

        #pragma unroll
        for (int ks = 0; ks < 4; ks++) {
            uint32_t ahf[2][4], alf[2][4], bf[4][2];
            #pragma unroll
            for (int mi = 0; mi < 2; mi++) {
                uint32_t off = (uint32_t)((wm * 32 + mi * 16 + (lane & 15)) * 144
                                          + ks * 32 + ((lane >> 4) * 16));
                ldm_x4(ahf[mi], stgb + off);
                if (mode == 1) ldm_x4(alf[mi], stgb + 27648u + off);
            }
            #pragma unroll
            for (int g = 0; g < 2; g++) {
                uint32_t off = 18432u
                    + (uint32_t)((ks * 16 + (lane & 15)) * 144
                                 + (wn * 32 + g * 16 + ((lane >> 4) * 8)) * 2);
                uint32_t t[4];
                ldm_x4t(t, stgb + off);
                bf[g*2][0]   = t[0]; bf[g*2][1]   = t[1];
                bf[g*2+1][0] = t[2]; bf[g*2+1][1] = t[3];
            }
            #pragma unroll
            for (int mi = 0; mi < 2; mi++)
                #pragma unroll
                for (int ni = 0; ni < 4; ni++) {
                    mma_f16(C[mi][ni], ahf[mi], bf[ni]);
                    if (mode == 1) mma_f16(C[mi][ni], alf[mi], bf[ni]);
                }
        }
        __syncthreads();
    }

    if (mode == 0) {
        const float s = INV_QKV * ((z == 0) ? 0.5f : (z == 1) ? 0.25f : 1.f);
        #pragma unroll
        for (int mi = 0; mi < 2; mi++)
            #pragma unroll
            for (int ni = 0; ni < 4; ni++) {
                int row = row0 + wm * 32 + mi * 16 + (lane >> 2);
                int col = col0 + wn * 32 + ni * 8 + (lane & 3) * 2;
                int hh = col >> 6, hd = col & 63;
                #pragma unroll
                for (int half = 0; half < 2; half++) {
                    int r = row + half * 8;
                    int b = r >> 11, l = r & 2047;
                    size_t off = (((size_t)(b * Hn + hh) * Ln + l) << 6) + hd;
                    float v0 = C[mi][ni][half*2]   * s;
                    float v1 = C[mi][ni][half*2+1] * s;
                    if (z == 0) {
                        uint32_t hw, lw;
                        packhl_h(v0, v1, hw, lw);
                        *(uint32_t*)(g_qh + off) = hw;
                        *(uint32_t*)(g_ql + off) = lw;
                    } else if (z == 1) {
                        *(uint32_t*)(g_k16 + off) = pack2h(v0, v1);
                    } else {
                        *(uint32_t*)(g_v16 + off) = pack2h(v0, v1);
                    }
                }
            }
    } else {
        #pragma unroll
        for (int mi = 0; mi < 2; mi++)
            #pragma unroll
            for (int ni = 0; ni < 4; ni++) {
                int row = row0 + wm * 32 + mi * 16 + (lane >> 2);
                int col = col0 + wn * 32 + ni * 8 + (lane & 3) * 2;
                float2 v0 = make_float2(C[mi][ni][0] * INV_OUT,
                                        C[mi][ni][1] * INV_OUT);
                float2 v1 = make_float2(C[mi][ni][2] * INV_OUT,
                                        C[mi][ni][3] * INV_OUT);
                *(float2*)(outp + (size_t)row * Dn + col) = v0;
                *(float2*)(outp + (size_t)(row + 8) * Dn + col) = v1;
            }
    }
}

// ---------------------------------------------------------------------------
// fp16 flash attention: Q hi/lo register-resident (2-pass S), P single-pass
// PV. K,V single fp16, double-buffered via cp.async.
// Stage (bytes): K 0 (9216), V 9216; stage size 18432, 2 stages.
// Q staged once above the ring (bytes [18432, 55296)), consumed pre-loop.
// ---------------------------------------------------------------------------
constexpr int QS = 72;
constexpr int A_STAGE = 18432;
constexpr int ATTN_SMEM_BYTES = 55296;

__global__ void __launch_bounds__(256) attn_kernel()
{
    extern __shared__ uint16_t smh[];
    const uint32_t sb = s2u(smh);

    const int qt   = blockIdx.x;
    const int h    = blockIdx.y;
    const int b    = blockIdx.z;
    const int tid  = threadIdx.x;
    const int lane = tid & 31;
    const int wid  = tid >> 5;
    const int r0   = wid * 16;

    const size_t base = ((size_t)(b * Hn + h) * Ln) * HDn;
    const uint16_t* qh_g = g_qh + base;
    const uint16_t* ql_g = g_ql + base;
    const uint16_t* k_g  = g_k16 + base;
    const uint16_t* v_g  = g_v16 + base;

    // Stage Q tile [128][64] hi/lo at elem offsets 9216 (QH) / 18432 (QL)
    #pragma unroll
    for (int i = 0; i < 4; i++) {
        int idx = tid + i * 256;
        int r = idx >> 3, c8 = idx & 7;
        size_t go = (size_t)(qt * 128 + r) * HDn + c8 * 8;
        *(uint4*)(smh + 9216 + r * QS + c8 * 8)  = *(const uint4*)(qh_g + go);
        *(uint4*)(smh + 18432 + r * QS + c8 * 8) = *(const uint4*)(ql_g + go);
    }

    const int ktmax = 2 * qt + 2;

    auto issue_kv = [&](int kt_, int s_) {
        uint32_t dstb = sb + (uint32_t)s_ * A_STAGE;
        #pragma unroll
        for (int i = 0; i < 4; i++) {
            int p = i >> 1;                    // 0 = K, 1 = V
            int local = (i & 1) * 256 + tid;
            int r = local >> 3, cc = local & 7;
            uint32_t dst = dstb + p * 9216u + (uint32_t)(r * QS + cc * 8) * 2;
            const uint16_t* gp = p ? v_g : k_g;
            cp16(dst, gp + (size_t)(kt_ * 64 + r) * HDn + cc * 8);
        }
    };
    issue_kv(0, 0);
    CP_COMMIT();
    __syncthreads();

    // Extract Q fragments to registers (reused every kt iteration)
    uint32_t qfh[4][4], qfl[4][4];
    #pragma unroll
    for (int ks = 0; ks < 4; ks++) {
        uint32_t qaddr = sb + (uint32_t)((9216 + (r0 + (lane & 15)) * QS
                          + ks * 16 + ((lane >> 4) * 8)) * 2);
        ldm_x4(qfh[ks], qaddr);
        ldm_x4(qfl[ks], qaddr + 9216u * 2);
    }
    __syncthreads();   // Q consumed; stage-1 region may be overwritten

    float m0 = -1e30f, m1 = -1e30f, l0 = 0.f, l1 = 0.f;
    float O[8][4];
    #pragma unroll
    for (int nt = 0; nt < 8; nt++)
        #pragma unroll
        for (int q = 0; q < 4; q++) O[nt][q] = 0.f;

    const int qbase = qt * 128 + r0;

    for (int kt = 0; kt < ktmax; kt++) {
        CP_WAIT0();
        __syncthreads();
        if (kt + 1 < ktmax) {
            issue_kv(kt + 1, (kt + 1) & 1);
            CP_COMMIT();
        }

        if (kt * 64 > qbase + 15) continue;

        const uint32_t stgb = sb + (uint32_t)(kt & 1) * A_STAGE;

        // ---- S = (Qh + Ql) * K^T ----
        float S[8][4];
        #pragma unroll
        for (int nt = 0; nt < 8; nt++)
            #pragma unroll
            for (int q = 0; q < 4; q++) S[nt][q] = 0.f;

        #pragma unroll
        for (int ks = 0; ks < 4; ks++) {
            #pragma unroll
            for (int ntp = 0; ntp < 4; ntp++) {
                uint32_t kaddr = stgb + (uint32_t)(((ntp * 16 + (lane & 7)
                                  + ((lane >> 4) << 3)) * QS
                                  + ((lane >> 3) & 1) * 8 + ks * 16) * 2);
                uint32_t bh[4];
                ldm_x4(bh, kaddr);
                mma_f16(S[2*ntp],   qfh[ks], bh);
                mma_f16(S[2*ntp],   qfl[ks], bh);
                mma_f16(S[2*ntp+1], qfh[ks], bh + 2);
                mma_f16(S[2*ntp+1], qfl[ks], bh + 2);
            }
        }

        // ---- causal mask (diagonal tiles only) ----
        if (kt * 64 + 63 > qbase) {
            int q0 = qbase + (lane >> 2);
            int q1 = q0 + 8;
            #pragma unroll
            for (int nt = 0; nt < 8; nt++) {
                int k0 = kt * 64 + nt * 8 + (lane & 3) * 2;
                if (k0     > q0) S[nt][0] = -1e30f;
                if (k0 + 1 > q0) S[nt][1] = -1e30f;
                if (k0     > q1) S[nt][2] = -1e30f;
                if (k0 + 1 > q1) S[nt][3] = -1e30f;
            }
        }

        // ---- online softmax ----
        float mx0 = -1e30f, mx1 = -1e30f;
        #pragma unroll
        for (int nt = 0; nt < 8; nt++) {
            mx0 = fmaxf(mx0, fmaxf(S[nt][0], S[nt][1]));
            mx1 = fmaxf(mx1, fmaxf(S[nt][2], S[nt][3]));
        }
        mx0 = fmaxf(mx0, __shfl_xor_sync(0xffffffffu, mx0, 1));
        mx0 = fmaxf(mx0, __shfl_xor_sync(0xffffffffu, mx0, 2));
        mx1 = fmaxf(mx1, __shfl_xor_sync(0xffffffffu, mx1, 1));
        mx1 = fmaxf(mx1, __shfl_xor_sync(0xffffffffu, mx1, 2));
        float nm0 = fmaxf(m0, mx0), nm1 = fmaxf(m1, mx1);
        float c0 = __expf(m0 - nm0), c1 = __expf(m1 - nm1);
        float s0 = 0.f, s1 = 0.f;
        #pragma unroll
        for (int nt = 0; nt < 8; nt++) {
            S[nt][0] = __expf(S[nt][0] - nm0);
            S[nt][1] = __expf(S[nt][1] - nm0);
            S[nt][2] = __expf(S[nt][2] - nm1);
            S[nt][3] = __expf(S[nt][3] - nm1);
            s0 += S[nt][0] + S[nt][1];
            s1 += S[nt][2] + S[nt][3];
        }
        s0 += __shfl_xor_sync(0xffffffffu, s0, 1);
        s0 += __shfl_xor_sync(0xffffffffu, s0, 2);
        s1 += __shfl_xor_sync(0xffffffffu, s1, 1);
        s1 += __shfl_xor_sync(0xffffffffu, s1, 2);
        m0 = nm0; m1 = nm1;
        l0 = l0 * c0 + s0;
        l1 = l1 * c1 + s1;
        #pragma unroll
        for (int nt = 0; nt < 8; nt++) {
            O[nt][0] *= c0; O[nt][1] *= c0;
            O[nt][2] *= c1; O[nt][3] *= c1;
        }

        // ---- O += P * V (single-pass P) ----
        #pragma unroll
        for (int g = 0; g < 4; g++) {
            uint32_t ah[4];
            ah[0] = pack2h(S[2*g][0],   S[2*g][1]);
            ah[1] = pack2h(S[2*g][2],   S[2*g][3]);
            ah[2] = pack2h(S[2*g+1][0], S[2*g+1][1]);
            ah[3] = pack2h(S[2*g+1][2], S[2*g+1][3]);
            #pragma unroll
            for (int ntp = 0; ntp < 4; ntp++) {
                uint32_t vaddr = stgb + 9216u
                    + (uint32_t)(((g * 16 + (lane & 15)) * QS
                                  + ntp * 16 + ((lane >> 4) << 3)) * 2);
                uint32_t vh[4];
                ldm_x4t(vh, vaddr);
                mma_f16(O[2*ntp],   ah, vh);
                mma_f16(O[2*ntp+1], ah, vh + 2);
            }
        }
    }

    // Finalize: scale by SC_Y/l, store y as fp16 hi/lo for out-proj
    float il0 = SC_Y / l0, il1 = SC_Y / l1;
    int rowg = qt * 128 + r0 + (lane >> 2);
    #pragma unroll
    for (int nt = 0; nt < 8; nt++) {
        int hd = nt * 8 + (lane & 3) * 2;
        size_t o0 = (size_t)(b * Ln + rowg) * Dn + h * 64 + hd;
        size_t o1 = (size_t)(b * Ln + rowg + 8) * Dn + h * 64 + hd;
        uint32_t hw, lw;
        packhl_h(O[nt][0] * il0, O[nt][1] * il0, hw, lw);
        *(uint32_t*)(g_yh + o0) = hw;
        *(uint32_t*)(g_yl + o0) = lw;
        packhl_h(O[nt][2] * il1, O[nt][3] * il1, hw, lw);
        *(uint32_t*)(g_yh + o1) = hw;
        *(uint32_t*)(g_yl + o1) = lw;
    }
}

// ---------------------------------------------------------------------------
extern "C" void kernel_launch(void* const* d_in, const int* in_sizes, int n_in,
                              void* d_out, int out_size)
{
    (void)in_sizes; (void)n_in; (void)out_size;
    const float* x  = (const float*)d_in[0];
    const float* Wq = (const float*)d_in[1];
    const float* Wk = (const float*)d_in[2];
    const float* Wv = (const float*)d_in[3];
    const float* Wo = (const float*)d_in[4];
    float* out = (float*)d_out;

    cudaFuncSetAttribute(gemm_mma_kernel,
                         cudaFuncAttributeMaxDynamicSharedMemorySize,
                         GEMM_SMEM1);
    cudaFuncSetAttribute(attn_kernel,
                         cudaFuncAttributeMaxDynamicSharedMemorySize,
                         ATTN_SMEM_BYTES);

    prep_kernel<<<8192, 256>>>(x, Wq, Wk, Wv, Wo);
    gemm_mma_kernel<<<dim3(Dn/64, NROW/128, 3), 256, GEMM_SMEM0>>>(nullptr, 0);
    attn_kernel<<<dim3(Ln/128, Hn, Bn), 256, ATTN_SMEM_BYTES>>>();
    gemm_mma_kernel<<<dim3(Dn/64, NROW/128, 1), 256, GEMM_SMEM1>>>(out, 1);
}

// round 13
// speedup vs baseline: 5.8377x; 1.4102x over previous
#include <cuda_runtime.h>
#include <cuda_bf16.h>
#include <cuda_fp16.h>
#include <cstdint>

// Problem constants
constexpr int Bn  = 2;
constexpr int Ln  = 2048;
constexpr int Dn  = 1024;
constexpr int Hn  = 16;
constexpr int HDn = 64;
constexpr int NROW = Bn * Ln;   // 4096
constexpr size_t PLANE = (size_t)Bn * Hn * Ln * HDn;  // 4M elems

// Scaling
constexpr float SC_X = 16.f;
constexpr float SC_W = 32.f;
constexpr float SC_Y = 256.f;
constexpr float INV_QKV = 1.f / (16.f * 32.f);    // 1/512
constexpr float INV_OUT = 1.f / (256.f * 32.f);   // 1/8192

// Scratch (device globals: allocation-free)
__device__ uint16_t g_x16[(size_t)NROW * Dn];     // fp16 of 16*x, [m][k]
__device__ uint16_t g_w16[(size_t)4 * Dn * Dn];   // fp16(32W): Wq,Wk,Wv,Wo [k][n]
__device__ uint16_t g_q16[PLANE];                 // fp16 of 0.5*q, [B,H,L,HD]
__device__ uint16_t g_k16[PLANE];                 // fp16 of 0.25*k
__device__ uint16_t g_v16[PLANE];                 // fp16 of v
__device__ uint16_t g_y16[(size_t)NROW * Dn];     // fp16 of 256*y

// ---------------------------------------------------------------------------
// Helpers
// ---------------------------------------------------------------------------
__device__ __forceinline__ uint32_t s2u(const void* p) {
    uint32_t a;
    asm("{ .reg .u64 t; cvta.to.shared.u64 t, %1; cvt.u32.u64 %0, t; }"
        : "=r"(a) : "l"(p));
    return a;
}
__device__ __forceinline__ void cp16(uint32_t dst, const void* src) {
    asm volatile("cp.async.cg.shared.global [%0], [%1], 16;"
                 :: "r"(dst), "l"(src) : "memory");
}
#define CP_COMMIT() asm volatile("cp.async.commit_group;" ::: "memory")
#define CP_WAIT0()  asm volatile("cp.async.wait_group 0;" ::: "memory")

__device__ __forceinline__ void ldm_x4(uint32_t* r, uint32_t a) {
    asm volatile("ldmatrix.sync.aligned.m8n8.x4.shared.b16 {%0,%1,%2,%3}, [%4];"
                 : "=r"(r[0]), "=r"(r[1]), "=r"(r[2]), "=r"(r[3]) : "r"(a));
}
__device__ __forceinline__ void ldm_x4t(uint32_t* r, uint32_t a) {
    asm volatile("ldmatrix.sync.aligned.m8n8.x4.trans.shared.b16 {%0,%1,%2,%3}, [%4];"
                 : "=r"(r[0]), "=r"(r[1]), "=r"(r[2]), "=r"(r[3]) : "r"(a));
}
__device__ __forceinline__ void mma_f16(float* c, const uint32_t* a,
                                        const uint32_t* b) {
    asm volatile(
        "mma.sync.aligned.m16n8k16.row.col.f32.f16.f16.f32 "
        "{%0,%1,%2,%3}, {%4,%5,%6,%7}, {%8,%9}, {%0,%1,%2,%3};"
        : "+f"(c[0]), "+f"(c[1]), "+f"(c[2]), "+f"(c[3])
        : "r"(a[0]), "r"(a[1]), "r"(a[2]), "r"(a[3]), "r"(b[0]), "r"(b[1]));
}
// fp16 helpers
__device__ __forceinline__ uint16_t hfu(float f) {
    __half h = __float2half_rn(f);
    return *(uint16_t*)&h;
}
__device__ __forceinline__ uint2 pack4h(float4 v) {
    uint16_t h0 = hfu(v.x), h1 = hfu(v.y), h2 = hfu(v.z), h3 = hfu(v.w);
    return make_uint2((uint32_t)h0 | ((uint32_t)h1 << 16),
                      (uint32_t)h2 | ((uint32_t)h3 << 16));
}
__device__ __forceinline__ uint32_t pack2h(float f0, float f1) {
    return (uint32_t)hfu(f0) | ((uint32_t)hfu(f1) << 16);
}

// ---------------------------------------------------------------------------
// Prep: x -> fp16(16x) single [m][k]; all 4 weights -> fp16(32W) [k][n].
// ---------------------------------------------------------------------------
__global__ void __launch_bounds__(256) prep_kernel(
    const float* __restrict__ x,
    const float* __restrict__ Wq, const float* __restrict__ Wk,
    const float* __restrict__ Wv, const float* __restrict__ Wo)
{
    int i = blockIdx.x * 256 + threadIdx.x;   // float4 index
    if (i < (1 << 20)) {
        float4 v = ((const float4*)x)[i];
        v.x *= SC_X; v.y *= SC_X; v.z *= SC_X; v.w *= SC_X;
        ((uint2*)g_x16)[i] = pack4h(v);
    } else {
        int j = i - (1 << 20);
        int slot = j >> 18;
        int off  = j & ((1 << 18) - 1);
        const float* w = (slot == 0) ? Wq : (slot == 1) ? Wk
                        : (slot == 2) ? Wv : Wo;
        float4 v = ((const float4*)w)[off];
        v.x *= SC_W; v.y *= SC_W; v.z *= SC_W; v.w *= SC_W;
        ((uint2*)g_w16)[((size_t)slot << 18) + off] = pack4h(v);
    }
}

// ---------------------------------------------------------------------------
// fp16 1-pass GEMM, BK=64: 128x64 CTA tile, 8 warps (4m x 2n), 32x32 warp tile.
// A = single fp16 [m][k] (x or y), B = single fp16 [k][n]. 2-stage cp.async,
// 16 chunks. Stage (bytes): A [0,18432) 128x144B; B [18432,27648) 64x144B.
// mode 0: A=x, slot z -> q/k/v fp16. mode 1: A=y, slot 3 (Wo) -> fp32 out.
// ---------------------------------------------------------------------------
constexpr int G_STAGE = 27648;
constexpr int GEMM_SMEM_BYTES = 2 * G_STAGE;   // 55296

__global__ void __launch_bounds__(256, 2) gemm_mma_kernel(
    float* __restrict__ outp, int mode)
{
    extern __shared__ uint16_t smg[];
    const uint32_t sb = s2u(smg);

    const int tid  = threadIdx.x;
    const int lane = tid & 31;
    const int w    = tid >> 5;
    const int wm   = w & 3;
    const int wn   = w >> 2;
    const int col0 = blockIdx.x * 64;
    const int row0 = blockIdx.y * 128;
    const int z    = blockIdx.z;

    const uint16_t* Ap = (mode == 0) ? g_x16 : g_y16;
    const int slot = (mode == 0) ? z : 3;
    const uint16_t* Bp = g_w16 + ((size_t)slot << 20);

    float C[2][4][4];
    #pragma unroll
    for (int mi = 0; mi < 2; mi++)
        #pragma unroll
        for (int ni = 0; ni < 4; ni++)
            #pragma unroll
            for (int q = 0; q < 4; q++) C[mi][ni][q] = 0.f;

    auto issue = [&](int c_, int s_) {
        uint32_t dstb = sb + (uint32_t)s_ * G_STAGE;
        int k0 = c_ * 64;
        #pragma unroll
        for (int i = 0; i < 4; i++) {
            int local = i * 256 + tid;
            int r = local >> 3, cc = local & 7;
            uint32_t dst = dstb + (uint32_t)(r * 144 + cc * 16);
            cp16(dst, Ap + (size_t)(row0 + r) * Dn + k0 + cc * 8);
        }
        #pragma unroll
        for (int i = 0; i < 2; i++) {
            int local = i * 256 + tid;
            int kk = local >> 3, cc = local & 7;
            uint32_t dst = dstb + 18432u + (uint32_t)(kk * 144 + cc * 16);
            cp16(dst, Bp + (size_t)(k0 + kk) * Dn + col0 + cc * 8);
        }
    };

    issue(0, 0);
    CP_COMMIT();

    for (int c = 0; c < 16; c++) {
        CP_WAIT0();
        __syncthreads();
        if (c + 1 < 16) {
            issue(c + 1, (c + 1) & 1);
            CP_COMMIT();
        }
        const uint32_t stgb = sb + (uint32_t)(c & 1) * G_STAGE;

        #pragma unroll
        for (int ks = 0; ks < 4; ks++) {
            uint32_t af[2][4], bf[4][2];
            #pragma unroll
            for (int mi = 0; mi < 2; mi++) {
                uint32_t off = (uint32_t)((wm * 32 + mi * 16 + (lane & 15)) * 144
                                          + ks * 32 + ((lane >> 4) * 16));
                ldm_x4(af[mi], stgb + off);
            }
            #pragma unroll
            for (int g = 0; g < 2; g++) {
                uint32_t off = 18432u
                    + (uint32_t)((ks * 16 + (lane & 15)) * 144
                                 + (wn * 32 + g * 16 + ((lane >> 4) * 8)) * 2);
                uint32_t t[4];
                ldm_x4t(t, stgb + off);
                bf[g*2][0]   = t[0]; bf[g*2][1]   = t[1];
                bf[g*2+1][0] = t[2]; bf[g*2+1][1] = t[3];
            }
            #pragma unroll
            for (int mi = 0; mi < 2; mi++)
                #pragma unroll
                for (int ni = 0; ni < 4; ni++)
                    mma_f16(C[mi][ni], af[mi], bf[ni]);
        }
        __syncthreads();
    }

    if (mode == 0) {
        // z=0: Q = 0.5*q fp16 (with K=0.25*k gives softmax scale 0.125)
        const float s = INV_QKV * ((z == 0) ? 0.5f : (z == 1) ? 0.25f : 1.f);
        uint16_t* dst = (z == 0) ? g_q16 : (z == 1) ? g_k16 : g_v16;
        #pragma unroll
        for (int mi = 0; mi < 2; mi++)
            #pragma unroll
            for (int ni = 0; ni < 4; ni++) {
                int row = row0 + wm * 32 + mi * 16 + (lane >> 2);
                int col = col0 + wn * 32 + ni * 8 + (lane & 3) * 2;
                int hh = col >> 6, hd = col & 63;
                #pragma unroll
                for (int half = 0; half < 2; half++) {
                    int r = row + half * 8;
                    int b = r >> 11, l = r & 2047;
                    size_t off = (((size_t)(b * Hn + hh) * Ln + l) << 6) + hd;
                    *(uint32_t*)(dst + off) =
                        pack2h(C[mi][ni][half*2] * s, C[mi][ni][half*2+1] * s);
                }
            }
    } else {
        #pragma unroll
        for (int mi = 0; mi < 2; mi++)
            #pragma unroll
            for (int ni = 0; ni < 4; ni++) {
                int row = row0 + wm * 32 + mi * 16 + (lane >> 2);
                int col = col0 + wn * 32 + ni * 8 + (lane & 3) * 2;
                float2 v0 = make_float2(C[mi][ni][0] * INV_OUT,
                                        C[mi][ni][1] * INV_OUT);
                float2 v1 = make_float2(C[mi][ni][2] * INV_OUT,
                                        C[mi][ni][3] * INV_OUT);
                *(float2*)(outp + (size_t)row * Dn + col) = v0;
                *(float2*)(outp + (size_t)(row + 8) * Dn + col) = v1;
            }
    }
}

// ---------------------------------------------------------------------------
// fp16 1-pass flash attention. Q single fp16, register-resident; K,V single
// fp16, double-buffered via cp.async; P single-pass.
// Stage (bytes): K 0 (9216), V 9216; stage size 18432, 2 stages = [0,36864).
// Q staged once at bytes [36864, 55296), consumed into registers pre-loop.
// ---------------------------------------------------------------------------
constexpr int QS = 72;
constexpr int A_STAGE = 18432;
constexpr int ATTN_SMEM_BYTES = 55296;

__global__ void __launch_bounds__(256) attn_kernel()
{
    extern __shared__ uint16_t smh[];
    const uint32_t sb = s2u(smh);

    const int qt   = blockIdx.x;
    const int h    = blockIdx.y;
    const int b    = blockIdx.z;
    const int tid  = threadIdx.x;
    const int lane = tid & 31;
    const int wid  = tid >> 5;
    const int r0   = wid * 16;

    const size_t base = ((size_t)(b * Hn + h) * Ln) * HDn;
    const uint16_t* q_g = g_q16 + base;
    const uint16_t* k_g = g_k16 + base;
    const uint16_t* v_g = g_v16 + base;

    // Stage Q tile [128][64] at elem offset 18432
    #pragma unroll
    for (int i = 0; i < 4; i++) {
        int idx = tid + i * 256;
        int r = idx >> 3, c8 = idx & 7;
        size_t go = (size_t)(qt * 128 + r) * HDn + c8 * 8;
        *(uint4*)(smh + 18432 + r * QS + c8 * 8) = *(const uint4*)(q_g + go);
    }

    const int ktmax = 2 * qt + 2;

    auto issue_kv = [&](int kt_, int s_) {
        uint32_t dstb = sb + (uint32_t)s_ * A_STAGE;
        #pragma unroll
        for (int i = 0; i < 4; i++) {
            int p = i >> 1;                    // 0 = K, 1 = V
            int local = (i & 1) * 256 + tid;
            int r = local >> 3, cc = local & 7;
            uint32_t dst = dstb + p * 9216u + (uint32_t)(r * QS + cc * 8) * 2;
            const uint16_t* gp = p ? v_g : k_g;
            cp16(dst, gp + (size_t)(kt_ * 64 + r) * HDn + cc * 8);
        }
    };
    issue_kv(0, 0);
    CP_COMMIT();
    __syncthreads();

    // Extract Q fragments to registers (reused every kt iteration)
    uint32_t qf[4][4];
    #pragma unroll
    for (int ks = 0; ks < 4; ks++) {
        uint32_t qaddr = sb + (uint32_t)((18432 + (r0 + (lane & 15)) * QS
                          + ks * 16 + ((lane >> 4) * 8)) * 2);
        ldm_x4(qf[ks], qaddr);
    }

    float m0 = -1e30f, m1 = -1e30f, l0 = 0.f, l1 = 0.f;
    float O[8][4];
    #pragma unroll
    for (int nt = 0; nt < 8; nt++)
        #pragma unroll
        for (int q = 0; q < 4; q++) O[nt][q] = 0.f;

    const int qbase = qt * 128 + r0;

    for (int kt = 0; kt < ktmax; kt++) {
        CP_WAIT0();
        __syncthreads();
        if (kt + 1 < ktmax) {
            issue_kv(kt + 1, (kt + 1) & 1);
            CP_COMMIT();
        }

        if (kt * 64 > qbase + 15) continue;

        const uint32_t stgb = sb + (uint32_t)(kt & 1) * A_STAGE;

        // ---- S = Q * K^T (single-pass) ----
        float S[8][4];
        #pragma unroll
        for (int nt = 0; nt < 8; nt++)
            #pragma unroll
            for (int q = 0; q < 4; q++) S[nt][q] = 0.f;

        #pragma unroll
        for (int ks = 0; ks < 4; ks++) {
            #pragma unroll
            for (int ntp = 0; ntp < 4; ntp++) {
                uint32_t kaddr = stgb + (uint32_t)(((ntp * 16 + (lane & 7)
                                  + ((lane >> 4) << 3)) * QS
                                  + ((lane >> 3) & 1) * 8 + ks * 16) * 2);
                uint32_t bh[4];
                ldm_x4(bh, kaddr);
                mma_f16(S[2*ntp],   qf[ks], bh);
                mma_f16(S[2*ntp+1], qf[ks], bh + 2);
            }
        }

        // ---- causal mask (diagonal tiles only) ----
        if (kt * 64 + 63 > qbase) {
            int q0 = qbase + (lane >> 2);
            int q1 = q0 + 8;
            #pragma unroll
            for (int nt = 0; nt < 8; nt++) {
                int k0 = kt * 64 + nt * 8 + (lane & 3) * 2;
                if (k0     > q0) S[nt][0] = -1e30f;
                if (k0 + 1 > q0) S[nt][1] = -1e30f;
                if (k0     > q1) S[nt][2] = -1e30f;
                if (k0 + 1 > q1) S[nt][3] = -1e30f;
            }
        }

        // ---- online softmax ----
        float mx0 = -1e30f, mx1 = -1e30f;
        #pragma unroll
        for (int nt = 0; nt < 8; nt++) {
            mx0 = fmaxf(mx0, fmaxf(S[nt][0], S[nt][1]));
            mx1 = fmaxf(mx1, fmaxf(S[nt][2], S[nt][3]));
        }
        mx0 = fmaxf(mx0, __shfl_xor_sync(0xffffffffu, mx0, 1));
        mx0 = fmaxf(mx0, __shfl_xor_sync(0xffffffffu, mx0, 2));
        mx1 = fmaxf(mx1, __shfl_xor_sync(0xffffffffu, mx1, 1));
        mx1 = fmaxf(mx1, __shfl_xor_sync(0xffffffffu, mx1, 2));
        float nm0 = fmaxf(m0, mx0), nm1 = fmaxf(m1, mx1);
        float c0 = __expf(m0 - nm0), c1 = __expf(m1 - nm1);
        float s0 = 0.f, s1 = 0.f;
        #pragma unroll
        for (int nt = 0; nt < 8; nt++) {
            S[nt][0] = __expf(S[nt][0] - nm0);
            S[nt][1] = __expf(S[nt][1] - nm0);
            S[nt][2] = __expf(S[nt][2] - nm1);
            S[nt][3] = __expf(S[nt][3] - nm1);
            s0 += S[nt][0] + S[nt][1];
            s1 += S[nt][2] + S[nt][3];
        }
        s0 += __shfl_xor_sync(0xffffffffu, s0, 1);
        s0 += __shfl_xor_sync(0xffffffffu, s0, 2);
        s1 += __shfl_xor_sync(0xffffffffu, s1, 1);
        s1 += __shfl_xor_sync(0xffffffffu, s1, 2);
        m0 = nm0; m1 = nm1;
        l0 = l0 * c0 + s0;
        l1 = l1 * c1 + s1;
        #pragma unroll
        for (int nt = 0; nt < 8; nt++) {
            O[nt][0] *= c0; O[nt][1] *= c0;
            O[nt][2] *= c1; O[nt][3] *= c1;
        }

        // ---- O += P * V (single-pass P) ----
        #pragma unroll
        for (int g = 0; g < 4; g++) {
            uint32_t ah[4];
            ah[0] = pack2h(S[2*g][0],   S[2*g][1]);
            ah[1] = pack2h(S[2*g][2],   S[2*g][3]);
            ah[2] = pack2h(S[2*g+1][0], S[2*g+1][1]);
            ah[3] = pack2h(S[2*g+1][2], S[2*g+1][3]);
            #pragma unroll
            for (int ntp = 0; ntp < 4; ntp++) {
                uint32_t vaddr = stgb + 9216u
                    + (uint32_t)(((g * 16 + (lane & 15)) * QS
                                  + ntp * 16 + ((lane >> 4) << 3)) * 2);
                uint32_t vh[4];
                ldm_x4t(vh, vaddr);
                mma_f16(O[2*ntp],   ah, vh);
                mma_f16(O[2*ntp+1], ah, vh + 2);
            }
        }
    }

    // Finalize: scale by SC_Y/l, store y as single fp16 for out-proj
    float il0 = SC_Y / l0, il1 = SC_Y / l1;
    int rowg = qt * 128 + r0 + (lane >> 2);
    #pragma unroll
    for (int nt = 0; nt < 8; nt++) {
        int hd = nt * 8 + (lane & 3) * 2;
        size_t o0 = (size_t)(b * Ln + rowg) * Dn + h * 64 + hd;
        size_t o1 = (size_t)(b * Ln + rowg + 8) * Dn + h * 64 + hd;
        *(uint32_t*)(g_y16 + o0) = pack2h(O[nt][0] * il0, O[nt][1] * il0);
        *(uint32_t*)(g_y16 + o1) = pack2h(O[nt][2] * il1, O[nt][3] * il1);
    }
}

// ---------------------------------------------------------------------------
extern "C" void kernel_launch(void* const* d_in, const int* in_sizes, int n_in,
                              void* d_out, int out_size)
{
    (void)in_sizes; (void)n_in; (void)out_size;
    const float* x  = (const float*)d_in[0];
    const float* Wq = (const float*)d_in[1];
    const float* Wk = (const float*)d_in[2];
    const float* Wv = (const float*)d_in[3];
    const float* Wo = (const float*)d_in[4];
    float* out = (float*)d_out;

    cudaFuncSetAttribute(gemm_mma_kernel,
                         cudaFuncAttributeMaxDynamicSharedMemorySize,
                         GEMM_SMEM_BYTES);
    cudaFuncSetAttribute(attn_kernel,
                         cudaFuncAttributeMaxDynamicSharedMemorySize,
                         ATTN_SMEM_BYTES);

    prep_kernel<<<8192, 256>>>(x, Wq, Wk, Wv, Wo);
    gemm_mma_kernel<<<dim3(Dn/64, NROW/128, 3), 256, GEMM_SMEM_BYTES>>>(nullptr, 0);
    attn_kernel<<<dim3(Ln/128, Hn, Bn), 256, ATTN_SMEM_BYTES>>>();
    gemm_mma_kernel<<<dim3(Dn/64, NROW/128, 1), 256, GEMM_SMEM_BYTES>>>(out, 1);
}

// round 14
// speedup vs baseline: 6.3335x; 1.0849x over previous
#include <cuda_runtime.h>
#include <cuda_bf16.h>
#include <cuda_fp16.h>
#include <cstdint>

// Problem constants
constexpr int Bn  = 2;
constexpr int Ln  = 2048;
constexpr int Dn  = 1024;
constexpr int Hn  = 16;
constexpr int HDn = 64;
constexpr int NROW = Bn * Ln;   // 4096
constexpr size_t PLANE = (size_t)Bn * Hn * Ln * HDn;  // 4M elems

// Scaling
constexpr float SC_X = 16.f;
constexpr float SC_W = 32.f;
constexpr float SC_Y = 256.f;
constexpr float INV_QKV = 1.f / (16.f * 32.f);    // 1/512
constexpr float INV_OUT = 1.f / (256.f * 32.f);   // 1/8192

// Scratch (device globals: allocation-free)
__device__ uint16_t g_x16[(size_t)NROW * Dn];     // fp16 of 16*x, [m][k]
__device__ uint16_t g_w16[(size_t)4 * Dn * Dn];   // fp16(32W): Wq,Wk,Wv,Wo [k][n]
__device__ uint16_t g_q16[PLANE];                 // fp16 of 0.5*q, [B,H,L,HD]
__device__ uint16_t g_k16[PLANE];                 // fp16 of 0.25*k
__device__ uint16_t g_v16[PLANE];                 // fp16 of v
__device__ uint16_t g_y16[(size_t)NROW * Dn];     // fp16 of 256*y

// ---------------------------------------------------------------------------
// Helpers
// ---------------------------------------------------------------------------
__device__ __forceinline__ uint32_t s2u(const void* p) {
    uint32_t a;
    asm("{ .reg .u64 t; cvta.to.shared.u64 t, %1; cvt.u32.u64 %0, t; }"
        : "=r"(a) : "l"(p));
    return a;
}
__device__ __forceinline__ void cp16(uint32_t dst, const void* src) {
    asm volatile("cp.async.cg.shared.global [%0], [%1], 16;"
                 :: "r"(dst), "l"(src) : "memory");
}
#define CP_COMMIT() asm volatile("cp.async.commit_group;" ::: "memory")
#define CP_WAIT0()  asm volatile("cp.async.wait_group 0;" ::: "memory")

__device__ __forceinline__ void ldm_x4(uint32_t* r, uint32_t a) {
    asm volatile("ldmatrix.sync.aligned.m8n8.x4.shared.b16 {%0,%1,%2,%3}, [%4];"
                 : "=r"(r[0]), "=r"(r[1]), "=r"(r[2]), "=r"(r[3]) : "r"(a));
}
__device__ __forceinline__ void ldm_x4t(uint32_t* r, uint32_t a) {
    asm volatile("ldmatrix.sync.aligned.m8n8.x4.trans.shared.b16 {%0,%1,%2,%3}, [%4];"
                 : "=r"(r[0]), "=r"(r[1]), "=r"(r[2]), "=r"(r[3]) : "r"(a));
}
__device__ __forceinline__ void mma_f16(float* c, const uint32_t* a,
                                        const uint32_t* b) {
    asm volatile(
        "mma.sync.aligned.m16n8k16.row.col.f32.f16.f16.f32 "
        "{%0,%1,%2,%3}, {%4,%5,%6,%7}, {%8,%9}, {%0,%1,%2,%3};"
        : "+f"(c[0]), "+f"(c[1]), "+f"(c[2]), "+f"(c[3])
        : "r"(a[0]), "r"(a[1]), "r"(a[2]), "r"(a[3]), "r"(b[0]), "r"(b[1]));
}
// fp16 helpers
__device__ __forceinline__ uint16_t hfu(float f) {
    __half h = __float2half_rn(f);
    return *(uint16_t*)&h;
}
__device__ __forceinline__ uint2 pack4h(float4 v) {
    uint16_t h0 = hfu(v.x), h1 = hfu(v.y), h2 = hfu(v.z), h3 = hfu(v.w);
    return make_uint2((uint32_t)h0 | ((uint32_t)h1 << 16),
                      (uint32_t)h2 | ((uint32_t)h3 << 16));
}
__device__ __forceinline__ uint32_t pack2h(float f0, float f1) {
    return (uint32_t)hfu(f0) | ((uint32_t)hfu(f1) << 16);
}

// ---------------------------------------------------------------------------
// Prep: x -> fp16(16x) single [m][k]; all 4 weights -> fp16(32W) [k][n].
// ---------------------------------------------------------------------------
__global__ void __launch_bounds__(256) prep_kernel(
    const float* __restrict__ x,
    const float* __restrict__ Wq, const float* __restrict__ Wk,
    const float* __restrict__ Wv, const float* __restrict__ Wo)
{
    int i = blockIdx.x * 256 + threadIdx.x;   // float4 index
    if (i < (1 << 20)) {
        float4 v = ((const float4*)x)[i];
        v.x *= SC_X; v.y *= SC_X; v.z *= SC_X; v.w *= SC_X;
        ((uint2*)g_x16)[i] = pack4h(v);
    } else {
        int j = i - (1 << 20);
        int slot = j >> 18;
        int off  = j & ((1 << 18) - 1);
        const float* w = (slot == 0) ? Wq : (slot == 1) ? Wk
                        : (slot == 2) ? Wv : Wo;
        float4 v = ((const float4*)w)[off];
        v.x *= SC_W; v.y *= SC_W; v.z *= SC_W; v.w *= SC_W;
        ((uint2*)g_w16)[((size_t)slot << 18) + off] = pack4h(v);
    }
}

// ---------------------------------------------------------------------------
// fp16 1-pass GEMM v2: 128x128 CTA tile, 8 warps (2m x 4n), warp tile 64x32.
// BK=64, 2-stage cp.async, 16 chunks.
// Stage (bytes): A [0, 18432)  128 rows x 144 B stride
//                B [18432, 35840)  64 k-rows x 272 B stride (128 cols + pad)
// Stage 35840 B x 2 = 71680 B dynamic smem. 2 CTAs/SM.
// mode 0: A=x, slot z -> q/k/v fp16. mode 1: A=y, slot 3 (Wo) -> fp32 out.
// ---------------------------------------------------------------------------
constexpr int G_STAGE = 35840;
constexpr int GEMM_SMEM_BYTES = 2 * G_STAGE;   // 71680

__global__ void __launch_bounds__(256, 2) gemm_mma_kernel(
    float* __restrict__ outp, int mode)
{
    extern __shared__ uint16_t smg[];
    const uint32_t sb = s2u(smg);

    const int tid  = threadIdx.x;
    const int lane = tid & 31;
    const int w    = tid >> 5;
    const int wm   = w >> 2;        // 0..1 (64 rows each)
    const int wn   = w & 3;         // 0..3 (32 cols each)
    const int col0 = blockIdx.x * 128;
    const int row0 = blockIdx.y * 128;
    const int z    = blockIdx.z;

    const uint16_t* Ap = (mode == 0) ? g_x16 : g_y16;
    const int slot = (mode == 0) ? z : 3;
    const uint16_t* Bp = g_w16 + ((size_t)slot << 20);

    float C[4][4][4];
    #pragma unroll
    for (int mi = 0; mi < 4; mi++)
        #pragma unroll
        for (int ni = 0; ni < 4; ni++)
            #pragma unroll
            for (int q = 0; q < 4; q++) C[mi][ni][q] = 0.f;

    auto issue = [&](int c_, int s_) {
        uint32_t dstb = sb + (uint32_t)s_ * G_STAGE;
        int k0 = c_ * 64;
        // A: 128 rows x 64 elems = 1024 cp16 (4/thread)
        #pragma unroll
        for (int i = 0; i < 4; i++) {
            int local = i * 256 + tid;
            int r = local >> 3, cc = local & 7;
            uint32_t dst = dstb + (uint32_t)(r * 144 + cc * 16);
            cp16(dst, Ap + (size_t)(row0 + r) * Dn + k0 + cc * 8);
        }
        // B: 64 k-rows x 128 cols = 1024 cp16 (4/thread)
        #pragma unroll
        for (int i = 0; i < 4; i++) {
            int local = i * 256 + tid;
            int kk = local >> 4, cc = local & 15;
            uint32_t dst = dstb + 18432u + (uint32_t)(kk * 272 + cc * 16);
            cp16(dst, Bp + (size_t)(k0 + kk) * Dn + col0 + cc * 8);
        }
    };

    issue(0, 0);
    CP_COMMIT();

    for (int c = 0; c < 16; c++) {
        CP_WAIT0();
        __syncthreads();
        if (c + 1 < 16) {
            issue(c + 1, (c + 1) & 1);
            CP_COMMIT();
        }
        const uint32_t stgb = sb + (uint32_t)(c & 1) * G_STAGE;

        #pragma unroll
        for (int ks = 0; ks < 4; ks++) {
            uint32_t af[4][4], bf[4][2];
            #pragma unroll
            for (int mi = 0; mi < 4; mi++) {
                uint32_t off = (uint32_t)((wm * 64 + mi * 16 + (lane & 15)) * 144
                                          + ks * 32 + ((lane >> 4) * 16));
                ldm_x4(af[mi], stgb + off);
            }
            #pragma unroll
            for (int g = 0; g < 2; g++) {
                uint32_t off = 18432u
                    + (uint32_t)((ks * 16 + (lane & 15)) * 272
                                 + (wn * 32 + g * 16 + ((lane >> 4) * 8)) * 2);
                uint32_t t[4];
                ldm_x4t(t, stgb + off);
                bf[g*2][0]   = t[0]; bf[g*2][1]   = t[1];
                bf[g*2+1][0] = t[2]; bf[g*2+1][1] = t[3];
            }
            #pragma unroll
            for (int mi = 0; mi < 4; mi++)
                #pragma unroll
                for (int ni = 0; ni < 4; ni++)
                    mma_f16(C[mi][ni], af[mi], bf[ni]);
        }
        __syncthreads();
    }

    if (mode == 0) {
        // z=0: Q = 0.5*q fp16 (with K=0.25*k gives softmax scale 0.125)
        const float s = INV_QKV * ((z == 0) ? 0.5f : (z == 1) ? 0.25f : 1.f);
        uint16_t* dst = (z == 0) ? g_q16 : (z == 1) ? g_k16 : g_v16;
        #pragma unroll
        for (int mi = 0; mi < 4; mi++)
            #pragma unroll
            for (int ni = 0; ni < 4; ni++) {
                int row = row0 + wm * 64 + mi * 16 + (lane >> 2);
                int col = col0 + wn * 32 + ni * 8 + (lane & 3) * 2;
                int hh = col >> 6, hd = col & 63;
                #pragma unroll
                for (int half = 0; half < 2; half++) {
                    int r = row + half * 8;
                    int b = r >> 11, l = r & 2047;
                    size_t off = (((size_t)(b * Hn + hh) * Ln + l) << 6) + hd;
                    *(uint32_t*)(dst + off) =
                        pack2h(C[mi][ni][half*2] * s, C[mi][ni][half*2+1] * s);
                }
            }
    } else {
        #pragma unroll
        for (int mi = 0; mi < 4; mi++)
            #pragma unroll
            for (int ni = 0; ni < 4; ni++) {
                int row = row0 + wm * 64 + mi * 16 + (lane >> 2);
                int col = col0 + wn * 32 + ni * 8 + (lane & 3) * 2;
                float2 v0 = make_float2(C[mi][ni][0] * INV_OUT,
                                        C[mi][ni][1] * INV_OUT);
                float2 v1 = make_float2(C[mi][ni][2] * INV_OUT,
                                        C[mi][ni][3] * INV_OUT);
                *(float2*)(outp + (size_t)row * Dn + col) = v0;
                *(float2*)(outp + (size_t)(row + 8) * Dn + col) = v1;
            }
    }
}

// ---------------------------------------------------------------------------
// fp16 1-pass flash attention (unchanged from round 13).
// ---------------------------------------------------------------------------
constexpr int QS = 72;
constexpr int A_STAGE = 18432;
constexpr int ATTN_SMEM_BYTES = 55296;

__global__ void __launch_bounds__(256) attn_kernel()
{
    extern __shared__ uint16_t smh[];
    const uint32_t sb = s2u(smh);

    const int qt   = blockIdx.x;
    const int h    = blockIdx.y;
    const int b    = blockIdx.z;
    const int tid  = threadIdx.x;
    const int lane = tid & 31;
    const int wid  = tid >> 5;
    const int r0   = wid * 16;

    const size_t base = ((size_t)(b * Hn + h) * Ln) * HDn;
    const uint16_t* q_g = g_q16 + base;
    const uint16_t* k_g = g_k16 + base;
    const uint16_t* v_g = g_v16 + base;

    // Stage Q tile [128][64] at elem offset 18432
    #pragma unroll
    for (int i = 0; i < 4; i++) {
        int idx = tid + i * 256;
        int r = idx >> 3, c8 = idx & 7;
        size_t go = (size_t)(qt * 128 + r) * HDn + c8 * 8;
        *(uint4*)(smh + 18432 + r * QS + c8 * 8) = *(const uint4*)(q_g + go);
    }

    const int ktmax = 2 * qt + 2;

    auto issue_kv = [&](int kt_, int s_) {
        uint32_t dstb = sb + (uint32_t)s_ * A_STAGE;
        #pragma unroll
        for (int i = 0; i < 4; i++) {
            int p = i >> 1;                    // 0 = K, 1 = V
            int local = (i & 1) * 256 + tid;
            int r = local >> 3, cc = local & 7;
            uint32_t dst = dstb + p * 9216u + (uint32_t)(r * QS + cc * 8) * 2;
            const uint16_t* gp = p ? v_g : k_g;
            cp16(dst, gp + (size_t)(kt_ * 64 + r) * HDn + cc * 8);
        }
    };
    issue_kv(0, 0);
    CP_COMMIT();
    __syncthreads();

    // Extract Q fragments to registers (reused every kt iteration)
    uint32_t qf[4][4];
    #pragma unroll
    for (int ks = 0; ks < 4; ks++) {
        uint32_t qaddr = sb + (uint32_t)((18432 + (r0 + (lane & 15)) * QS
                          + ks * 16 + ((lane >> 4) * 8)) * 2);
        ldm_x4(qf[ks], qaddr);
    }

    float m0 = -1e30f, m1 = -1e30f, l0 = 0.f, l1 = 0.f;
    float O[8][4];
    #pragma unroll
    for (int nt = 0; nt < 8; nt++)
        #pragma unroll
        for (int q = 0; q < 4; q++) O[nt][q] = 0.f;

    const int qbase = qt * 128 + r0;

    for (int kt = 0; kt < ktmax; kt++) {
        CP_WAIT0();
        __syncthreads();
        if (kt + 1 < ktmax) {
            issue_kv(kt + 1, (kt + 1) & 1);
            CP_COMMIT();
        }

        if (kt * 64 > qbase + 15) continue;

        const uint32_t stgb = sb + (uint32_t)(kt & 1) * A_STAGE;

        // ---- S = Q * K^T ----
        float S[8][4];
        #pragma unroll
        for (int nt = 0; nt < 8; nt++)
            #pragma unroll
            for (int q = 0; q < 4; q++) S[nt][q] = 0.f;

        #pragma unroll
        for (int ks = 0; ks < 4; ks++) {
            #pragma unroll
            for (int ntp = 0; ntp < 4; ntp++) {
                uint32_t kaddr = stgb + (uint32_t)(((ntp * 16 + (lane & 7)
                                  + ((lane >> 4) << 3)) * QS
                                  + ((lane >> 3) & 1) * 8 + ks * 16) * 2);
                uint32_t bh[4];
                ldm_x4(bh, kaddr);
                mma_f16(S[2*ntp],   qf[ks], bh);
                mma_f16(S[2*ntp+1], qf[ks], bh + 2);
            }
        }

        // ---- causal mask (diagonal tiles only) ----
        if (kt * 64 + 63 > qbase) {
            int q0 = qbase + (lane >> 2);
            int q1 = q0 + 8;
            #pragma unroll
            for (int nt = 0; nt < 8; nt++) {
                int k0 = kt * 64 + nt * 8 + (lane & 3) * 2;
                if (k0     > q0) S[nt][0] = -1e30f;
                if (k0 + 1 > q0) S[nt][1] = -1e30f;
                if (k0     > q1) S[nt][2] = -1e30f;
                if (k0 + 1 > q1) S[nt][3] = -1e30f;
            }
        }

        // ---- online softmax ----
        float mx0 = -1e30f, mx1 = -1e30f;
        #pragma unroll
        for (int nt = 0; nt < 8; nt++) {
            mx0 = fmaxf(mx0, fmaxf(S[nt][0], S[nt][1]));
            mx1 = fmaxf(mx1, fmaxf(S[nt][2], S[nt][3]));
        }
        mx0 = fmaxf(mx0, __shfl_xor_sync(0xffffffffu, mx0, 1));
        mx0 = fmaxf(mx0, __shfl_xor_sync(0xffffffffu, mx0, 2));
        mx1 = fmaxf(mx1, __shfl_xor_sync(0xffffffffu, mx1, 1));
        mx1 = fmaxf(mx1, __shfl_xor_sync(0xffffffffu, mx1, 2));
        float nm0 = fmaxf(m0, mx0), nm1 = fmaxf(m1, mx1);
        float c0 = __expf(m0 - nm0), c1 = __expf(m1 - nm1);
        float s0 = 0.f, s1 = 0.f;
        #pragma unroll
        for (int nt = 0; nt < 8; nt++) {
            S[nt][0] = __expf(S[nt][0] - nm0);
            S[nt][1] = __expf(S[nt][1] - nm0);
            S[nt][2] = __expf(S[nt][2] - nm1);
            S[nt][3] = __expf(S[nt][3] - nm1);
            s0 += S[nt][0] + S[nt][1];
            s1 += S[nt][2] + S[nt][3];
        }
        s0 += __shfl_xor_sync(0xffffffffu, s0, 1);
        s0 += __shfl_xor_sync(0xffffffffu, s0, 2);
        s1 += __shfl_xor_sync(0xffffffffu, s1, 1);
        s1 += __shfl_xor_sync(0xffffffffu, s1, 2);
        m0 = nm0; m1 = nm1;
        l0 = l0 * c0 + s0;
        l1 = l1 * c1 + s1;
        #pragma unroll
        for (int nt = 0; nt < 8; nt++) {
            O[nt][0] *= c0; O[nt][1] *= c0;
            O[nt][2] *= c1; O[nt][3] *= c1;
        }

        // ---- O += P * V ----
        #pragma unroll
        for (int g = 0; g < 4; g++) {
            uint32_t ah[4];
            ah[0] = pack2h(S[2*g][0],   S[2*g][1]);
            ah[1] = pack2h(S[2*g][2],   S[2*g][3]);
            ah[2] = pack2h(S[2*g+1][0], S[2*g+1][1]);
            ah[3] = pack2h(S[2*g+1][2], S[2*g+1][3]);
            #pragma unroll
            for (int ntp = 0; ntp < 4; ntp++) {
                uint32_t vaddr = stgb + 9216u
                    + (uint32_t)(((g * 16 + (lane & 15)) * QS
                                  + ntp * 16 + ((lane >> 4) << 3)) * 2);
                uint32_t vh[4];
                ldm_x4t(vh, vaddr);
                mma_f16(O[2*ntp],   ah, vh);
                mma_f16(O[2*ntp+1], ah, vh + 2);
            }
        }
    }

    // Finalize: scale by SC_Y/l, store y as single fp16 for out-proj
    float il0 = SC_Y / l0, il1 = SC_Y / l1;
    int rowg = qt * 128 + r0 + (lane >> 2);
    #pragma unroll
    for (int nt = 0; nt < 8; nt++) {
        int hd = nt * 8 + (lane & 3) * 2;
        size_t o0 = (size_t)(b * Ln + rowg) * Dn + h * 64 + hd;
        size_t o1 = (size_t)(b * Ln + rowg + 8) * Dn + h * 64 + hd;
        *(uint32_t*)(g_y16 + o0) = pack2h(O[nt][0] * il0, O[nt][1] * il0);
        *(uint32_t*)(g_y16 + o1) = pack2h(O[nt][2] * il1, O[nt][3] * il1);
    }
}

// ---------------------------------------------------------------------------
extern "C" void kernel_launch(void* const* d_in, const int* in_sizes, int n_in,
                              void* d_out, int out_size)
{
    (void)in_sizes; (void)n_in; (void)out_size;
    const float* x  = (const float*)d_in[0];
    const float* Wq = (const float*)d_in[1];
    const float* Wk = (const float*)d_in[2];
    const float* Wv = (const float*)d_in[3];
    const float* Wo = (const float*)d_in[4];
    float* out = (float*)d_out;

    cudaFuncSetAttribute(gemm_mma_kernel,
                         cudaFuncAttributeMaxDynamicSharedMemorySize,
                         GEMM_SMEM_BYTES);
    cudaFuncSetAttribute(attn_kernel,
                         cudaFuncAttributeMaxDynamicSharedMemorySize,
                         ATTN_SMEM_BYTES);

    prep_kernel<<<8192, 256>>>(x, Wq, Wk, Wv, Wo);
    gemm_mma_kernel<<<dim3(Dn/128, NROW/128, 3), 256, GEMM_SMEM_BYTES>>>(nullptr, 0);
    attn_kernel<<<dim3(Ln/128, Hn, Bn), 256, ATTN_SMEM_BYTES>>>();
    gemm_mma_kernel<<<dim3(Dn/128, NROW/128, 1), 256, GEMM_SMEM_BYTES>>>(out, 1);
}